// round 1
// baseline (speedup 1.0000x reference)
#include <cuda_runtime.h>
#include <cstddef>

#define NNODES 65536
#define CIN    128
#define COUT   128
#define NDIR   9
#define NCAT   (NDIR * COUT)   // 1152

// ---------------- scratch (static device globals; no allocation) ----------------
__device__ float g_Y[(size_t)NNODES * NCAT];   // 302 MB: per-direction transformed features
__device__ float g_acc[(size_t)NNODES * COUT]; // 32 MB: scatter accumulator (L2-resident)
__device__ float g_acc3[(size_t)NNODES * COUT];
__device__ float g_h1[(size_t)NNODES * COUT];
__device__ float g_h2[(size_t)NNODES * COUT];
__device__ float g_Wcat[CIN * NCAT];           // packed [K=128][9*128]

// ---------------- utility kernels ----------------
__global__ void zero_kernel(float* __restrict__ p, int n4) {
    int i = blockIdx.x * blockDim.x + threadIdx.x;
    if (i < n4) reinterpret_cast<float4*>(p)[i] = make_float4(0.f, 0.f, 0.f, 0.f);
}

// W: [NDIR][CIN][COUT] -> Wc: [CIN][NDIR*COUT] with Wc[k][d*COUT+c] = W[d][k][c]
__global__ void pack_kernel(const float* __restrict__ W, float* __restrict__ Wc) {
    int idx = blockIdx.x * blockDim.x + threadIdx.x;
    if (idx >= NDIR * CIN * COUT) return;
    int d = idx >> 14;            // / (128*128)
    int rem = idx & 16383;
    int k = rem >> 7;
    int c = rem & 127;
    Wc[k * NCAT + d * COUT + c] = W[idx];
}

// ---------------- GEMM: C[M,ldb] = A[M,128] @ B[128,ldb], fp32 via packed fma.rn.f32x2
// Tile 128x128, BK=8, 256 threads, 8x8 per thread (4 col-pairs).
__global__ void __launch_bounds__(256, 2)
gemm128_kernel(const float* __restrict__ A, const float* __restrict__ B,
               float* __restrict__ C, int ldb) {
    __shared__ float As[8][128];  // transposed: [k][row]
    __shared__ float Bs[8][128];  // [k][col]

    const int tid = threadIdx.x;
    const int tx = tid & 15;      // col group
    const int ty = tid >> 4;      // row group
    const int rowBase = blockIdx.y * 128;
    const int colBase = blockIdx.x * 128;

    // global load assignments
    const int ar = tid >> 1;           // 0..127 (row within tile)
    const int ak = (tid & 1) * 4;      // k quad
    const int bk = tid >> 5;           // 0..7
    const int bc = (tid & 31) * 4;     // col quad

    const float* Aptr = A + (size_t)(rowBase + ar) * 128 + ak;
    const float* Bptr = B + (size_t)bk * ldb + colBase + bc;

    float4 a_pref = *reinterpret_cast<const float4*>(Aptr);
    float4 b_pref = *reinterpret_cast<const float4*>(Bptr);

    unsigned long long acc[8][4];
#pragma unroll
    for (int i = 0; i < 8; i++)
#pragma unroll
        for (int j = 0; j < 4; j++) acc[i][j] = 0ull;

#pragma unroll 1
    for (int t = 0; t < 16; ++t) {
        __syncthreads();
        As[ak + 0][ar] = a_pref.x;
        As[ak + 1][ar] = a_pref.y;
        As[ak + 2][ar] = a_pref.z;
        As[ak + 3][ar] = a_pref.w;
        *reinterpret_cast<float4*>(&Bs[bk][bc]) = b_pref;
        __syncthreads();

        if (t < 15) {
            a_pref = *reinterpret_cast<const float4*>(Aptr + (t + 1) * 8);
            b_pref = *reinterpret_cast<const float4*>(Bptr + (size_t)(t + 1) * 8 * ldb);
        }

#pragma unroll
        for (int kk = 0; kk < 8; ++kk) {
            float4 a0 = *reinterpret_cast<const float4*>(&As[kk][ty * 8]);
            float4 a1 = *reinterpret_cast<const float4*>(&As[kk][ty * 8 + 4]);
            ulonglong2 b01 = *reinterpret_cast<const ulonglong2*>(&Bs[kk][tx * 8]);
            ulonglong2 b23 = *reinterpret_cast<const ulonglong2*>(&Bs[kk][tx * 8 + 4]);
            unsigned long long bp[4] = {b01.x, b01.y, b23.x, b23.y};
            float av[8] = {a0.x, a0.y, a0.z, a0.w, a1.x, a1.y, a1.z, a1.w};
#pragma unroll
            for (int i = 0; i < 8; i++) {
                unsigned long long ad;
                asm("mov.b64 %0, {%1, %1};" : "=l"(ad) : "f"(av[i]));
#pragma unroll
                for (int j = 0; j < 4; j++) {
                    asm("fma.rn.f32x2 %0, %1, %2, %0;"
                        : "+l"(acc[i][j]) : "l"(ad), "l"(bp[j]));
                }
            }
        }
    }

    // epilogue
    union U { unsigned long long u; float2 f; };
#pragma unroll
    for (int i = 0; i < 8; i++) {
        U u0, u1, u2, u3;
        u0.u = acc[i][0]; u1.u = acc[i][1]; u2.u = acc[i][2]; u3.u = acc[i][3];
        float4 w0 = make_float4(u0.f.x, u0.f.y, u1.f.x, u1.f.y);
        float4 w1 = make_float4(u2.f.x, u2.f.y, u3.f.x, u3.f.y);
        size_t off = (size_t)(rowBase + ty * 8 + i) * ldb + colBase + tx * 8;
        *reinterpret_cast<float4*>(C + off) = w0;
        *reinterpret_cast<float4*>(C + off + 4) = w1;
    }
}

// ---------------- scatter: one warp per edge; 512B gather + v4 atomic reduce
// MODE 0: Y is [N,1152], use row slice sel*128. MODE 1: Y is [N,128], only sel==0 edges.
template <int MODE>
__global__ void scatter_kernel(const float* __restrict__ Y, const int* __restrict__ src,
                               const int* __restrict__ dst, const int* __restrict__ sel,
                               float* __restrict__ acc, int E) {
    int w = (blockIdx.x * blockDim.x + threadIdx.x) >> 5;
    int lane = threadIdx.x & 31;
    if (w >= E) return;
    int q = __ldg(sel + w);
    if (MODE == 1 && q != 0) return;
    int s = __ldg(src + w);
    int d = __ldg(dst + w);
    const float* yp = (MODE == 0) ? (Y + (size_t)s * NCAT + q * COUT)
                                  : (Y + (size_t)s * COUT);
    float4 v = *reinterpret_cast<const float4*>(yp + lane * 4);
    float* op = acc + (size_t)d * COUT + lane * 4;
    asm volatile("red.global.add.v4.f32 [%0], {%1,%2,%3,%4};"
                 :: "l"(op), "f"(v.x), "f"(v.y), "f"(v.z), "f"(v.w)
                 : "memory");
}

// ---------------- fused bias + BN(eval) + ELU ----------------
__device__ __forceinline__ float elu1(float t) { return t > 0.f ? t : expm1f(t); }

__global__ void bnelu_kernel(const float* __restrict__ acc, const float* __restrict__ b,
                             const float* __restrict__ g, const float* __restrict__ be,
                             const float* __restrict__ rm, const float* __restrict__ rv,
                             float* __restrict__ h) {
    int i = blockIdx.x * blockDim.x + threadIdx.x;  // one float4
    if (i >= NNODES * COUT / 4) return;
    float4 v = reinterpret_cast<const float4*>(acc)[i];
    int c0 = (i * 4) & (COUT - 1);
    float o[4] = {v.x, v.y, v.z, v.w};
    float4 r;
    float* rr = reinterpret_cast<float*>(&r);
#pragma unroll
    for (int j = 0; j < 4; j++) {
        int c = c0 + j;
        float s = __ldg(g + c) * rsqrtf(__ldg(rv + c) + 1e-5f);
        float t = (o[j] + __ldg(b + c) - __ldg(rm + c)) * s + __ldg(be + c);
        rr[j] = elu1(t);
    }
    reinterpret_cast<float4*>(h)[i] = r;
}

// out = ELU(BN3(h2 + acc3 + b3))
__global__ void final_kernel(const float* __restrict__ h2, const float* __restrict__ acc3,
                             const float* __restrict__ b, const float* __restrict__ g,
                             const float* __restrict__ be, const float* __restrict__ rm,
                             const float* __restrict__ rv, float* __restrict__ out) {
    int i = blockIdx.x * blockDim.x + threadIdx.x;  // one float4
    if (i >= NNODES * COUT / 4) return;
    float4 a = reinterpret_cast<const float4*>(h2)[i];
    float4 c4 = reinterpret_cast<const float4*>(acc3)[i];
    int c0 = (i * 4) & (COUT - 1);
    float o[4] = {a.x + c4.x, a.y + c4.y, a.z + c4.z, a.w + c4.w};
    float4 r;
    float* rr = reinterpret_cast<float*>(&r);
#pragma unroll
    for (int j = 0; j < 4; j++) {
        int c = c0 + j;
        float s = __ldg(g + c) * rsqrtf(__ldg(rv + c) + 1e-5f);
        float t = (o[j] + __ldg(b + c) - __ldg(rm + c)) * s + __ldg(be + c);
        rr[j] = elu1(t);
    }
    reinterpret_cast<float4*>(out)[i] = r;
}

// ---------------- launch ----------------
extern "C" void kernel_launch(void* const* d_in, const int* in_sizes, int n_in,
                              void* d_out, int out_size) {
    const float* x   = (const float*)d_in[0];
    const int*   ei  = (const int*)d_in[1];
    const int*   sel = (const int*)d_in[2];
    const float* W1  = (const float*)d_in[3];
    const float* b1  = (const float*)d_in[4];
    const float* g1  = (const float*)d_in[5];
    const float* be1 = (const float*)d_in[6];
    const float* rm1 = (const float*)d_in[7];
    const float* rv1 = (const float*)d_in[8];
    const float* W2  = (const float*)d_in[9];
    const float* b2  = (const float*)d_in[10];
    const float* g2  = (const float*)d_in[11];
    const float* be2 = (const float*)d_in[12];
    const float* rm2 = (const float*)d_in[13];
    const float* rv2 = (const float*)d_in[14];
    const float* W3  = (const float*)d_in[15];
    const float* b3  = (const float*)d_in[16];
    const float* g3  = (const float*)d_in[17];
    const float* be3 = (const float*)d_in[18];
    const float* rm3 = (const float*)d_in[19];
    const float* rv3 = (const float*)d_in[20];
    float* out = (float*)d_out;

    const int E = in_sizes[2];
    const int* src = ei;
    const int* dst = ei + E;

    float *Y, *acc, *acc3, *h1, *h2, *Wc;
    cudaGetSymbolAddress((void**)&Y, g_Y);
    cudaGetSymbolAddress((void**)&acc, g_acc);
    cudaGetSymbolAddress((void**)&acc3, g_acc3);
    cudaGetSymbolAddress((void**)&h1, g_h1);
    cudaGetSymbolAddress((void**)&h2, g_h2);
    cudaGetSymbolAddress((void**)&Wc, g_Wcat);

    const int nc4 = NNODES * COUT / 4;
    const int ew_blocks = (nc4 + 255) / 256;
    const int z_blocks = ew_blocks;
    const int pack_blocks = (NDIR * CIN * COUT + 255) / 256;
    const int sc_blocks = (int)(((long long)E * 32 + 255) / 256);
    dim3 gemm_grid9(NCAT / 128, NNODES / 128);
    dim3 gemm_grid1(1, NNODES / 128);

    // ---- layer 1: SelectionConv(9) + BN + ELU ----
    pack_kernel<<<pack_blocks, 256>>>(W1, Wc);
    zero_kernel<<<z_blocks, 256>>>(acc, nc4);
    gemm128_kernel<<<gemm_grid9, 256>>>(x, Wc, Y, NCAT);
    scatter_kernel<0><<<sc_blocks, 256>>>(Y, src, dst, sel, acc, E);
    bnelu_kernel<<<ew_blocks, 256>>>(acc, b1, g1, be1, rm1, rv1, h1);

    // ---- layer 2: SelectionConv(9) + BN + ELU ----
    pack_kernel<<<pack_blocks, 256>>>(W2, Wc);
    zero_kernel<<<z_blocks, 256>>>(acc, nc4);
    gemm128_kernel<<<gemm_grid9, 256>>>(h1, Wc, Y, NCAT);
    scatter_kernel<0><<<sc_blocks, 256>>>(Y, src, dst, sel, acc, E);
    bnelu_kernel<<<ew_blocks, 256>>>(acc, b2, g2, be2, rm2, rv2, h2);

    // ---- shortcut: SelectionConv(1x1, sel==0) ----
    zero_kernel<<<z_blocks, 256>>>(acc3, nc4);
    gemm128_kernel<<<gemm_grid1, 256>>>(x, W3, Y, COUT);  // W3[0] is already [128,128] row-major
    scatter_kernel<1><<<sc_blocks, 256>>>(Y, src, dst, sel, acc3, E);

    // ---- combine: ELU(BN3(h2 + sc)) ----
    final_kernel<<<ew_blocks, 256>>>(h2, acc3, b3, g3, be3, rm3, rv3, out);
}

// round 3
// speedup vs baseline: 1.9390x; 1.9390x over previous
#include <cuda_runtime.h>
#include <cuda_bf16.h>
#include <cstdint>
#include <cstddef>

#define NNODES 65536
#define CIN    128
#define COUT   128
#define NDIR   9
#define NCAT   (NDIR * COUT)   // 1152

// ---------------- scratch (static device globals; no allocation) ----------------
__device__ __align__(256) float g_Y[(size_t)NNODES * NCAT];    // 302 MB
__device__ __align__(256) float g_Ysc[(size_t)NNODES * COUT];  // 32 MB shortcut Y
__device__ __align__(256) float g_acc[(size_t)NNODES * COUT];
__device__ __align__(256) float g_acc3[(size_t)NNODES * COUT];
__device__ __align__(256) float g_h1[(size_t)NNODES * COUT];
__device__ __align__(256) float g_h2[(size_t)NNODES * COUT];
__device__ __align__(256) __nv_bfloat16 g_Abx[(size_t)NNODES * 256]; // [N][hi128|lo128]
__device__ __align__(256) __nv_bfloat16 g_Abh[(size_t)NNODES * 256];
__device__ __align__(256) __nv_bfloat16 g_Wb1[(size_t)NCAT * 256];   // [n][hi128|lo128] (k contiguous)
__device__ __align__(256) __nv_bfloat16 g_Wb2[(size_t)NCAT * 256];
__device__ __align__(256) __nv_bfloat16 g_Wb3[(size_t)COUT * 256];

// ---------------- PTX helpers (sm_80-era only: cp.async / ldmatrix / mma.sync) ----------------
__device__ __forceinline__ uint32_t smem_u32(const void* p) {
    uint32_t a;
    asm("{ .reg .u64 t; cvta.to.shared.u64 t, %1; cvt.u32.u64 %0, t; }" : "=r"(a) : "l"(p));
    return a;
}
__device__ __forceinline__ void cp_async16(uint32_t saddr, const void* gptr) {
    asm volatile("cp.async.cg.shared.global [%0], [%1], 16;" :: "r"(saddr), "l"(gptr) : "memory");
}
__device__ __forceinline__ void cp_commit() {
    asm volatile("cp.async.commit_group;" ::: "memory");
}
__device__ __forceinline__ void ldsm_x4(uint32_t* r, uint32_t addr) {
    asm volatile("ldmatrix.sync.aligned.m8n8.x4.shared.b16 {%0,%1,%2,%3}, [%4];"
                 : "=r"(r[0]), "=r"(r[1]), "=r"(r[2]), "=r"(r[3]) : "r"(addr));
}
__device__ __forceinline__ void mma16816(float* d, const uint32_t* a, const uint32_t* b) {
    asm volatile(
        "mma.sync.aligned.m16n8k16.row.col.f32.bf16.bf16.f32 "
        "{%0,%1,%2,%3}, {%4,%5,%6,%7}, {%8,%9}, {%0,%1,%2,%3};"
        : "+f"(d[0]), "+f"(d[1]), "+f"(d[2]), "+f"(d[3])
        : "r"(a[0]), "r"(a[1]), "r"(a[2]), "r"(a[3]), "r"(b[0]), "r"(b[1]));
}

// ---------------- GEMM: C[M,ldc](tile 128x128) = Ahi@Whi + Ahi@Wlo + Alo@Whi ----------------
// Ab: [Mrows][256] bf16 (hi|lo, k contiguous).  Bb: [ncols][256] bf16 (hi|lo, k contiguous).
// Effective K = 384 as 6 chunks of 64 with per-chunk offsets into the 256-wide rows.
static constexpr int STAGE_BYTES = 32768;            // A 16KB + B 16KB
static constexpr int SMEM_BYTES  = 2 * STAGE_BYTES + 1024;

__global__ void __launch_bounds__(256, 2)
gemm_bf16x3_kernel(const __nv_bfloat16* __restrict__ Ab,
                   const __nv_bfloat16* __restrict__ Bb,
                   float* __restrict__ C, int ldc)
{
    extern __shared__ char smem_raw[];
    char* sdata = (char*)(((uintptr_t)smem_raw + 1023) & ~(uintptr_t)1023);
    const uint32_t sb = smem_u32(sdata);

    const int tid = threadIdx.x;
    const int wid = tid >> 5, lane = tid & 31;
    const int warpM = wid & 1;        // 2 warps over M
    const int warpN = wid >> 1;       // 4 warps over N
    const int rowBase = blockIdx.y << 7;
    const int colBase = blockIdx.x << 7;

    // chunk -> (A elem offset, B elem offset) within the 256-wide hi|lo rows
    const int aOff[6] = {0, 64, 0, 64, 128, 192};
    const int bOff[6] = {0, 64, 128, 192, 0, 64};

    float acc[4][4][4];
#pragma unroll
    for (int mt = 0; mt < 4; mt++)
#pragma unroll
        for (int nt = 0; nt < 4; nt++)
#pragma unroll
            for (int j = 0; j < 4; j++) acc[mt][nt][j] = 0.f;

    // ---- stage loader: 128 rows x 64 bf16 (=128B) each for A and B, SW128 XOR swizzle
    auto load_stage = [&](int c, int stage) {
        uint32_t aBase = sb + stage * STAGE_BYTES;
        uint32_t bBase = aBase + 16384;
#pragma unroll
        for (int i = 0; i < 4; i++) {
            int idx = tid + (i << 8);          // 0..1023
            int row = idx >> 3, g = idx & 7;   // row, 16B group
            uint32_t so = (uint32_t)row * 128 + (uint32_t)((g ^ (row & 7)) << 4);
            cp_async16(aBase + so, Ab + (size_t)(rowBase + row) * 256 + aOff[c] + g * 8);
        }
#pragma unroll
        for (int i = 0; i < 4; i++) {
            int idx = tid + (i << 8);
            int row = idx >> 3, g = idx & 7;
            uint32_t so = (uint32_t)row * 128 + (uint32_t)((g ^ (row & 7)) << 4);
            cp_async16(bBase + so, Bb + (size_t)(colBase + row) * 256 + bOff[c] + g * 8);
        }
        cp_commit();
    };

    load_stage(0, 0);
    load_stage(1, 1);

#pragma unroll 1
    for (int c = 0; c < 6; c++) {
        if (c < 5) asm volatile("cp.async.wait_group 1;" ::: "memory");
        else       asm volatile("cp.async.wait_group 0;" ::: "memory");
        __syncthreads();

        const int stage = c & 1;
        uint32_t aBase = sb + stage * STAGE_BYTES;
        uint32_t bBase = aBase + 16384;

#pragma unroll
        for (int ks = 0; ks < 4; ks++) {
            uint32_t aF[4][4];
#pragma unroll
            for (int mt = 0; mt < 4; mt++) {
                int row = warpM * 64 + mt * 16 + (lane & 15);
                int g = ks * 2 + (lane >> 4);
                ldsm_x4(aF[mt], aBase + (uint32_t)row * 128 + (uint32_t)((g ^ (row & 7)) << 4));
            }
            uint32_t bF[4][2];
#pragma unroll
            for (int p = 0; p < 2; p++) {
                int n = warpN * 32 + p * 16 + ((lane >> 4) << 3) + (lane & 7);
                int g = ks * 2 + ((lane >> 3) & 1);
                uint32_t r[4];
                ldsm_x4(r, bBase + (uint32_t)n * 128 + (uint32_t)((g ^ (n & 7)) << 4));
                bF[2 * p][0] = r[0]; bF[2 * p][1] = r[1];
                bF[2 * p + 1][0] = r[2]; bF[2 * p + 1][1] = r[3];
            }
#pragma unroll
            for (int mt = 0; mt < 4; mt++)
#pragma unroll
                for (int nt = 0; nt < 4; nt++)
                    mma16816(acc[mt][nt], aF[mt], bF[nt]);
        }

        __syncthreads();
        if (c + 2 < 6) load_stage(c + 2, stage);
    }

    // ---- epilogue: direct global stores (float2 per mma quad-row)
#pragma unroll
    for (int mt = 0; mt < 4; mt++) {
        int r0 = rowBase + warpM * 64 + mt * 16 + (lane >> 2);
#pragma unroll
        for (int nt = 0; nt < 4; nt++) {
            int c0 = colBase + warpN * 32 + nt * 8 + ((lane & 3) << 1);
            float* p0 = C + (size_t)r0 * ldc + c0;
            float* p1 = p0 + (size_t)8 * ldc;
            *reinterpret_cast<float2*>(p0) = make_float2(acc[mt][nt][0], acc[mt][nt][1]);
            *reinterpret_cast<float2*>(p1) = make_float2(acc[mt][nt][2], acc[mt][nt][3]);
        }
    }
}

// ---------------- prep kernels ----------------
// X fp32 [N][128] -> Ab bf16 [N][256] = [hi(128) | lo(128)]
__global__ void prepA_kernel(const float* __restrict__ X, __nv_bfloat16* __restrict__ Ab) {
    int i = blockIdx.x * blockDim.x + threadIdx.x;   // over N*32 float4s
    if (i >= NNODES * 32) return;
    int row = i >> 5, q = i & 31;
    float4 x = reinterpret_cast<const float4*>(X)[i];
    float xs[4] = {x.x, x.y, x.z, x.w};
    __nv_bfloat16 h[4], l[4];
#pragma unroll
    for (int j = 0; j < 4; j++) {
        h[j] = __float2bfloat16(xs[j]);
        l[j] = __float2bfloat16(xs[j] - __bfloat162float(h[j]));
    }
    __nv_bfloat16* base = Ab + (size_t)row * 256 + q * 4;
    reinterpret_cast<__nv_bfloat162*>(base)[0] = __nv_bfloat162(h[0], h[1]);
    reinterpret_cast<__nv_bfloat162*>(base)[1] = __nv_bfloat162(h[2], h[3]);
    reinterpret_cast<__nv_bfloat162*>(base + 128)[0] = __nv_bfloat162(l[0], l[1]);
    reinterpret_cast<__nv_bfloat162*>(base + 128)[1] = __nv_bfloat162(l[2], l[3]);
}

// W fp32 [ndir][128 k][128 c] -> Wb bf16 [ndir*128 n][256] with Wb[n][k]=hi, Wb[n][128+k]=lo
__global__ void prepW_kernel(const float* __restrict__ W, __nv_bfloat16* __restrict__ Wb, int total) {
    int idx = blockIdx.x * blockDim.x + threadIdx.x;
    if (idx >= total) return;
    int d = idx >> 14;
    int k = (idx >> 7) & 127;
    int c = idx & 127;
    float w = W[idx];
    __nv_bfloat16 hi = __float2bfloat16(w);
    __nv_bfloat16 lo = __float2bfloat16(w - __bfloat162float(hi));
    size_t row = (size_t)(d * 128 + c);
    Wb[row * 256 + k] = hi;
    Wb[row * 256 + 128 + k] = lo;
}

// ---------------- scatter: 4 edges per warp (MLP=4), v4 red.global ----------------
template <int MODE>
__global__ void scatter_kernel(const float* __restrict__ Y, const int* __restrict__ src,
                               const int* __restrict__ dst, const int* __restrict__ sel,
                               float* __restrict__ acc, int E) {
    int w = (blockIdx.x * blockDim.x + threadIdx.x) >> 5;
    int lane = threadIdx.x & 31;
    int e0 = w * 4;
    if (e0 >= E) return;
    float4 v[4];
    float* op[4];
    bool ok[4];
#pragma unroll
    for (int e = 0; e < 4; e++) {
        int id = e0 + e;
        ok[e] = (id < E);
        if (!ok[e]) continue;
        int q = __ldg(sel + id);
        if (MODE == 1 && q != 0) { ok[e] = false; continue; }
        int s = __ldg(src + id);
        int d = __ldg(dst + id);
        const float* yp = (MODE == 0) ? (Y + (size_t)s * NCAT + q * COUT)
                                      : (Y + (size_t)s * COUT);
        v[e] = *reinterpret_cast<const float4*>(yp + lane * 4);
        op[e] = acc + (size_t)d * COUT + lane * 4;
    }
#pragma unroll
    for (int e = 0; e < 4; e++) {
        if (!ok[e]) continue;
        asm volatile("red.global.add.v4.f32 [%0], {%1,%2,%3,%4};"
                     :: "l"(op[e]), "f"(v[e].x), "f"(v[e].y), "f"(v[e].z), "f"(v[e].w)
                     : "memory");
    }
}

// ---------------- fused bias + BN(eval) + ELU ----------------
__device__ __forceinline__ float elu1(float t) { return t > 0.f ? t : expm1f(t); }

__global__ void bnelu_kernel(const float* __restrict__ acc, const float* __restrict__ b,
                             const float* __restrict__ g, const float* __restrict__ be,
                             const float* __restrict__ rm, const float* __restrict__ rv,
                             float* __restrict__ h) {
    int i = blockIdx.x * blockDim.x + threadIdx.x;
    if (i >= NNODES * COUT / 4) return;
    float4 v = reinterpret_cast<const float4*>(acc)[i];
    int c0 = (i * 4) & (COUT - 1);
    float o[4] = {v.x, v.y, v.z, v.w};
    float4 r;
    float* rr = reinterpret_cast<float*>(&r);
#pragma unroll
    for (int j = 0; j < 4; j++) {
        int c = c0 + j;
        float s = __ldg(g + c) * rsqrtf(__ldg(rv + c) + 1e-5f);
        float t = (o[j] + __ldg(b + c) - __ldg(rm + c)) * s + __ldg(be + c);
        rr[j] = elu1(t);
    }
    reinterpret_cast<float4*>(h)[i] = r;
}

__global__ void final_kernel(const float* __restrict__ h2, const float* __restrict__ acc3,
                             const float* __restrict__ b, const float* __restrict__ g,
                             const float* __restrict__ be, const float* __restrict__ rm,
                             const float* __restrict__ rv, float* __restrict__ out) {
    int i = blockIdx.x * blockDim.x + threadIdx.x;
    if (i >= NNODES * COUT / 4) return;
    float4 a = reinterpret_cast<const float4*>(h2)[i];
    float4 c4 = reinterpret_cast<const float4*>(acc3)[i];
    int c0 = (i * 4) & (COUT - 1);
    float o[4] = {a.x + c4.x, a.y + c4.y, a.z + c4.z, a.w + c4.w};
    float4 r;
    float* rr = reinterpret_cast<float*>(&r);
#pragma unroll
    for (int j = 0; j < 4; j++) {
        int c = c0 + j;
        float s = __ldg(g + c) * rsqrtf(__ldg(rv + c) + 1e-5f);
        float t = (o[j] + __ldg(b + c) - __ldg(rm + c)) * s + __ldg(be + c);
        rr[j] = elu1(t);
    }
    reinterpret_cast<float4*>(out)[i] = r;
}

// ---------------- launch ----------------
extern "C" void kernel_launch(void* const* d_in, const int* in_sizes, int n_in,
                              void* d_out, int out_size) {
    const float* x   = (const float*)d_in[0];
    const int*   ei  = (const int*)d_in[1];
    const int*   sel = (const int*)d_in[2];
    const float* W1  = (const float*)d_in[3];
    const float* b1  = (const float*)d_in[4];
    const float* g1  = (const float*)d_in[5];
    const float* be1 = (const float*)d_in[6];
    const float* rm1 = (const float*)d_in[7];
    const float* rv1 = (const float*)d_in[8];
    const float* W2  = (const float*)d_in[9];
    const float* b2  = (const float*)d_in[10];
    const float* g2  = (const float*)d_in[11];
    const float* be2 = (const float*)d_in[12];
    const float* rm2 = (const float*)d_in[13];
    const float* rv2 = (const float*)d_in[14];
    const float* W3  = (const float*)d_in[15];
    const float* b3  = (const float*)d_in[16];
    const float* g3  = (const float*)d_in[17];
    const float* be3 = (const float*)d_in[18];
    const float* rm3 = (const float*)d_in[19];
    const float* rv3 = (const float*)d_in[20];
    float* out = (float*)d_out;

    const int E = in_sizes[2];
    const int* src = ei;
    const int* dst = ei + E;

    float *Y, *Ysc, *acc, *acc3, *h1, *h2;
    __nv_bfloat16 *Abx, *Abh, *Wb1, *Wb2, *Wb3;
    cudaGetSymbolAddress((void**)&Y, g_Y);
    cudaGetSymbolAddress((void**)&Ysc, g_Ysc);
    cudaGetSymbolAddress((void**)&acc, g_acc);
    cudaGetSymbolAddress((void**)&acc3, g_acc3);
    cudaGetSymbolAddress((void**)&h1, g_h1);
    cudaGetSymbolAddress((void**)&h2, g_h2);
    cudaGetSymbolAddress((void**)&Abx, g_Abx);
    cudaGetSymbolAddress((void**)&Abh, g_Abh);
    cudaGetSymbolAddress((void**)&Wb1, g_Wb1);
    cudaGetSymbolAddress((void**)&Wb2, g_Wb2);
    cudaGetSymbolAddress((void**)&Wb3, g_Wb3);

    cudaFuncSetAttribute(gemm_bf16x3_kernel,
                         cudaFuncAttributeMaxDynamicSharedMemorySize, SMEM_BYTES);

    const size_t accBytes = (size_t)NNODES * COUT * sizeof(float);
    const int nc4 = NNODES * COUT / 4;
    const int ew_blocks = (nc4 + 255) / 256;
    const int prepA_blocks = (NNODES * 32 + 255) / 256;
    const int prepW9_blocks = (NDIR * CIN * COUT + 255) / 256;
    const int prepW1_blocks = (CIN * COUT + 255) / 256;
    const int sc_warps = (E + 3) / 4;
    const int sc_blocks = (sc_warps * 32 + 255) / 256;
    dim3 gemm_grid9(NCAT / 128, NNODES / 128);
    dim3 gemm_grid1(1, NNODES / 128);

    // ---- prep ----
    prepW_kernel<<<prepW9_blocks, 256>>>(W1, Wb1, NDIR * CIN * COUT);
    prepW_kernel<<<prepW9_blocks, 256>>>(W2, Wb2, NDIR * CIN * COUT);
    prepW_kernel<<<prepW1_blocks, 256>>>(W3, Wb3, CIN * COUT);
    prepA_kernel<<<prepA_blocks, 256>>>(x, Abx);

    // ---- layer 1 + shortcut GEMMs (both use Abx) ----
    cudaMemsetAsync(acc, 0, accBytes);
    cudaMemsetAsync(acc3, 0, accBytes);
    gemm_bf16x3_kernel<<<gemm_grid9, 256, SMEM_BYTES>>>(Abx, Wb1, Y, NCAT);
    gemm_bf16x3_kernel<<<gemm_grid1, 256, SMEM_BYTES>>>(Abx, Wb3, Ysc, COUT);
    scatter_kernel<0><<<sc_blocks, 256>>>(Y, src, dst, sel, acc, E);
    scatter_kernel<1><<<sc_blocks, 256>>>(Ysc, src, dst, sel, acc3, E);
    bnelu_kernel<<<ew_blocks, 256>>>(acc, b1, g1, be1, rm1, rv1, h1);

    // ---- layer 2 ----
    prepA_kernel<<<prepA_blocks, 256>>>(h1, Abh);
    cudaMemsetAsync(acc, 0, accBytes);
    gemm_bf16x3_kernel<<<gemm_grid9, 256, SMEM_BYTES>>>(Abh, Wb2, Y, NCAT);
    scatter_kernel<0><<<sc_blocks, 256>>>(Y, src, dst, sel, acc, E);
    bnelu_kernel<<<ew_blocks, 256>>>(acc, b2, g2, be2, rm2, rv2, h2);

    // ---- combine: ELU(BN3(h2 + sc)) ----
    final_kernel<<<ew_blocks, 256>>>(h2, acc3, b3, g3, be3, rm3, rv3, out);
}

// round 4
// speedup vs baseline: 2.8494x; 1.4695x over previous
#include <cuda_runtime.h>
#include <cuda_fp16.h>
#include <cstdint>
#include <cstddef>

#define NNODES 65536
#define CIN    128
#define COUT   128
#define NDIR   9
#define NTILES (NNODES / 128)        // 512
#define NBUCK  (NTILES * NDIR)       // 4608
#define EMAX   1048576

// ---------------- scratch (static device globals; no allocation) ----------------
__device__ __align__(256) float g_acc[(size_t)NNODES * COUT];
__device__ __align__(256) float g_acc3[(size_t)NNODES * COUT];
__device__ __align__(256) float g_h1[(size_t)NNODES * COUT];
__device__ __align__(256) float g_h2[(size_t)NNODES * COUT];
__device__ __align__(256) __half g_Abx[(size_t)NNODES * 256]; // [N][hi128|lo128]
__device__ __align__(256) __half g_Abh[(size_t)NNODES * 256];
__device__ __align__(256) __half g_Wb1[(size_t)NDIR * 128 * 128]; // [d*128+c][k]
__device__ __align__(256) __half g_Wb2[(size_t)NDIR * 128 * 128];
__device__ __align__(256) __half g_Wb3[(size_t)128 * 128];
__device__ int g_cnt[NBUCK];
__device__ int g_boffs[NBUCK + 1];
__device__ int g_cur[NBUCK];
__device__ uint32_t g_ebuf[EMAX];    // packed: dst[0:16) | localsrc[16:23)

// ---------------- PTX helpers ----------------
__device__ __forceinline__ uint32_t smem_u32(const void* p) {
    uint32_t a;
    asm("{ .reg .u64 t; cvta.to.shared.u64 t, %1; cvt.u32.u64 %0, t; }" : "=r"(a) : "l"(p));
    return a;
}
__device__ __forceinline__ void cp_async16(uint32_t saddr, const void* gptr) {
    asm volatile("cp.async.cg.shared.global [%0], [%1], 16;" :: "r"(saddr), "l"(gptr) : "memory");
}
__device__ __forceinline__ void cp_commit() {
    asm volatile("cp.async.commit_group;" ::: "memory");
}
template <int N>
__device__ __forceinline__ void cp_wait() {
    asm volatile("cp.async.wait_group %0;" :: "n"(N) : "memory");
}
__device__ __forceinline__ void ldsm_x4(uint32_t* r, uint32_t addr) {
    asm volatile("ldmatrix.sync.aligned.m8n8.x4.shared.b16 {%0,%1,%2,%3}, [%4];"
                 : "=r"(r[0]), "=r"(r[1]), "=r"(r[2]), "=r"(r[3]) : "r"(addr));
}
__device__ __forceinline__ void mma16816(float* d, const uint32_t* a, const uint32_t* b) {
    asm volatile(
        "mma.sync.aligned.m16n8k16.row.col.f32.f16.f16.f32 "
        "{%0,%1,%2,%3}, {%4,%5,%6,%7}, {%8,%9}, {%0,%1,%2,%3};"
        : "+f"(d[0]), "+f"(d[1]), "+f"(d[2]), "+f"(d[3])
        : "r"(a[0]), "r"(a[1]), "r"(a[2]), "r"(a[3]), "r"(b[0]), "r"(b[1]));
}

// SMEM layout (dynamic, 1024-aligned base):
//   [0, 16K)      A stage 0
//   [16K, 32K)    A stage 1
//   [32K, 48K)    B chunk 0 (resident)
//   [48K, 64K)    B chunk 1 (resident)
//   after mainloop, the whole region is reused as Y tile: float[128][132]
static constexpr int YSTRIDE = 132;
static constexpr int SMEM_BYTES = 1024 + 128 * YSTRIDE * 4;  // 68608

// ---------------- fused GEMM + scatter ----------------
// grid = (nd, 512). CTA computes Y tile [128 nodes x 128 cols] for direction blockIdx.x
// (K=256: [Ahi|Alo] fp16 @ [W;W] fp16), then scatters bucket edges into gacc.
__global__ void __launch_bounds__(256, 2)
gemm_scatter_kernel(const __half* __restrict__ Ab,   // [N][256] hi|lo
                    const __half* __restrict__ Bb,   // [nd*128][128] fp16, k contiguous
                    const int* __restrict__ boffs,
                    const uint32_t* __restrict__ ebuf,
                    float* __restrict__ gacc)
{
    extern __shared__ char smem_raw[];
    char* sdata = (char*)(((uintptr_t)smem_raw + 1023) & ~(uintptr_t)1023);
    const uint32_t sb = smem_u32(sdata);

    const int tid = threadIdx.x;
    const int wid = tid >> 5, lane = tid & 31;
    const int warpM = wid & 1;
    const int warpN = wid >> 1;
    const int rowBase = blockIdx.y << 7;
    const int colBase = blockIdx.x << 7;   // weight row block (direction*128)
    const int bucket = blockIdx.y * NDIR + blockIdx.x;

    const int aOff[4] = {0, 64, 128, 192};   // chunk -> A element offset in 256-wide row

    float cfrag[4][4][4];
#pragma unroll
    for (int mt = 0; mt < 4; mt++)
#pragma unroll
        for (int nt = 0; nt < 4; nt++)
#pragma unroll
            for (int j = 0; j < 4; j++) cfrag[mt][nt][j] = 0.f;

    auto load_A = [&](int c, int stage) {
        uint32_t aBase = sb + stage * 16384;
#pragma unroll
        for (int i = 0; i < 4; i++) {
            int idx = tid + (i << 8);          // 0..1023
            int row = idx >> 3, g = idx & 7;
            uint32_t so = (uint32_t)row * 128 + (uint32_t)((g ^ (row & 7)) << 4);
            cp_async16(aBase + so, Ab + (size_t)(rowBase + row) * 256 + aOff[c] + g * 8);
        }
    };
    auto load_B = [&]() {
#pragma unroll
        for (int i = 0; i < 8; i++) {
            int idx = tid + (i << 8);          // 0..2047
            int ch = idx >> 10;                // chunk 0/1
            int row = (idx >> 3) & 127, g = idx & 7;
            uint32_t so = 32768u + (uint32_t)ch * 16384 + (uint32_t)row * 128
                        + (uint32_t)((g ^ (row & 7)) << 4);
            cp_async16(sb + so, Bb + (size_t)(colBase + row) * 128 + ch * 64 + g * 8);
        }
    };

    load_B();
    load_A(0, 0);
    cp_commit();
    load_A(1, 1);
    cp_commit();

#pragma unroll 1
    for (int c = 0; c < 4; c++) {
        if (c < 3) cp_wait<1>();
        else       cp_wait<0>();
        __syncthreads();

        uint32_t aBase = sb + (uint32_t)(c & 1) * 16384;
        uint32_t bBase = sb + 32768u + (uint32_t)(c & 1) * 16384;

#pragma unroll
        for (int ks = 0; ks < 4; ks++) {
            uint32_t aF[4][4];
#pragma unroll
            for (int mt = 0; mt < 4; mt++) {
                int row = warpM * 64 + mt * 16 + (lane & 15);
                int g = ks * 2 + (lane >> 4);
                ldsm_x4(aF[mt], aBase + (uint32_t)row * 128 + (uint32_t)((g ^ (row & 7)) << 4));
            }
            uint32_t bF[4][2];
#pragma unroll
            for (int p = 0; p < 2; p++) {
                int n = warpN * 32 + p * 16 + ((lane >> 4) << 3) + (lane & 7);
                int g = ks * 2 + ((lane >> 3) & 1);
                uint32_t r[4];
                ldsm_x4(r, bBase + (uint32_t)n * 128 + (uint32_t)((g ^ (n & 7)) << 4));
                bF[2 * p][0] = r[0]; bF[2 * p][1] = r[1];
                bF[2 * p + 1][0] = r[2]; bF[2 * p + 1][1] = r[3];
            }
#pragma unroll
            for (int mt = 0; mt < 4; mt++)
#pragma unroll
                for (int nt = 0; nt < 4; nt++)
                    mma16816(cfrag[mt][nt], aF[mt], bF[nt]);
        }

        __syncthreads();
        if (c < 2) {
            load_A(c + 2, c & 1);
            cp_commit();
        }
    }

    // ---- write Y tile to SMEM (reuse pipeline region) ----
    float* yt = reinterpret_cast<float*>(sdata);
#pragma unroll
    for (int mt = 0; mt < 4; mt++) {
        int r0 = warpM * 64 + mt * 16 + (lane >> 2);
#pragma unroll
        for (int nt = 0; nt < 4; nt++) {
            int c0 = warpN * 32 + nt * 8 + ((lane & 3) << 1);
            yt[r0 * YSTRIDE + c0]       = cfrag[mt][nt][0];
            yt[r0 * YSTRIDE + c0 + 1]   = cfrag[mt][nt][1];
            yt[(r0 + 8) * YSTRIDE + c0]     = cfrag[mt][nt][2];
            yt[(r0 + 8) * YSTRIDE + c0 + 1] = cfrag[mt][nt][3];
        }
    }
    __syncthreads();

    // ---- scatter this bucket's edges ----
    const int e0 = __ldg(boffs + bucket);
    const int e1 = __ldg(boffs + bucket + 1);
    for (int e = e0 + wid; e < e1; e += 8) {
        uint32_t pk = __ldg(ebuf + e);
        int ls = pk >> 16;             // local src row (0..127)
        int dst = pk & 0xFFFF;
        float4 v = *reinterpret_cast<const float4*>(yt + (size_t)ls * YSTRIDE + lane * 4);
        float* op = gacc + (size_t)dst * COUT + lane * 4;
        asm volatile("red.global.add.v4.f32 [%0], {%1,%2,%3,%4};"
                     :: "l"(op), "f"(v.x), "f"(v.y), "f"(v.z), "f"(v.w)
                     : "memory");
    }
}

// ---------------- edge bucketing ----------------
__global__ void hist_kernel(const int* __restrict__ src, const int* __restrict__ sel,
                            int* __restrict__ cnt, int E) {
    int i = blockIdx.x * blockDim.x + threadIdx.x;
    if (i >= E) return;
    int b = (__ldg(src + i) >> 7) * NDIR + __ldg(sel + i);
    atomicAdd(cnt + b, 1);
}

__global__ void scan_kernel(const int* __restrict__ cnt, int* __restrict__ boffs,
                            int* __restrict__ cur) {
    __shared__ int part[256];
    __shared__ int partpf[257];
    const int PER = NBUCK / 256;   // 18
    int t = threadIdx.x;
    int base = t * PER;
    int loc[PER];
    int s = 0;
#pragma unroll
    for (int j = 0; j < PER; j++) { loc[j] = s; s += cnt[base + j]; }
    part[t] = s;
    __syncthreads();
    if (t == 0) {
        int r = 0;
        for (int i = 0; i < 256; i++) { partpf[i] = r; r += part[i]; }
        partpf[256] = r;
    }
    __syncthreads();
    int off = partpf[t];
#pragma unroll
    for (int j = 0; j < PER; j++) {
        int v = off + loc[j];
        boffs[base + j] = v;
        cur[base + j] = v;
    }
    if (t == 255) boffs[NBUCK] = partpf[256];
}

__global__ void fill_kernel(const int* __restrict__ src, const int* __restrict__ dst,
                            const int* __restrict__ sel, int* __restrict__ cur,
                            uint32_t* __restrict__ ebuf, int E) {
    int i = blockIdx.x * blockDim.x + threadIdx.x;
    if (i >= E) return;
    int s = __ldg(src + i);
    int b = (s >> 7) * NDIR + __ldg(sel + i);
    int p = atomicAdd(cur + b, 1);
    ebuf[p] = (uint32_t)(__ldg(dst + i) & 0xFFFF) | ((uint32_t)(s & 127) << 16);
}

// ---------------- prep kernels ----------------
// X fp32 [N][128] -> Ab fp16 [N][256] = [hi(128) | lo(128)]
__global__ void prepA_kernel(const float* __restrict__ X, __half* __restrict__ Ab) {
    int i = blockIdx.x * blockDim.x + threadIdx.x;   // over N*32 float4s
    if (i >= NNODES * 32) return;
    int row = i >> 5, q = i & 31;
    float4 x = reinterpret_cast<const float4*>(X)[i];
    float xs[4] = {x.x, x.y, x.z, x.w};
    __half h[4], l[4];
#pragma unroll
    for (int j = 0; j < 4; j++) {
        h[j] = __float2half_rn(xs[j]);
        l[j] = __float2half_rn(xs[j] - __half2float(h[j]));
    }
    __half* base = Ab + (size_t)row * 256 + q * 4;
    reinterpret_cast<__half2*>(base)[0] = __halves2half2(h[0], h[1]);
    reinterpret_cast<__half2*>(base)[1] = __halves2half2(h[2], h[3]);
    reinterpret_cast<__half2*>(base + 128)[0] = __halves2half2(l[0], l[1]);
    reinterpret_cast<__half2*>(base + 128)[1] = __halves2half2(l[2], l[3]);
}

// W fp32 [d][k][c] -> Wb fp16 [(d*128+c)][k]
__global__ void prepW_kernel(const float* __restrict__ W, __half* __restrict__ Wb, int total) {
    int idx = blockIdx.x * blockDim.x + threadIdx.x;
    if (idx >= total) return;
    int d = idx >> 14;
    int k = (idx >> 7) & 127;
    int c = idx & 127;
    Wb[((size_t)d * 128 + c) * 128 + k] = __float2half_rn(W[idx]);
}

// ---------------- fused bias + BN(eval) + ELU ----------------
__device__ __forceinline__ float elu1(float t) { return t > 0.f ? t : expm1f(t); }

__global__ void bnelu_kernel(const float* __restrict__ acc, const float* __restrict__ b,
                             const float* __restrict__ g, const float* __restrict__ be,
                             const float* __restrict__ rm, const float* __restrict__ rv,
                             float* __restrict__ h) {
    int i = blockIdx.x * blockDim.x + threadIdx.x;
    if (i >= NNODES * COUT / 4) return;
    float4 v = reinterpret_cast<const float4*>(acc)[i];
    int c0 = (i * 4) & (COUT - 1);
    float o[4] = {v.x, v.y, v.z, v.w};
    float4 r;
    float* rr = reinterpret_cast<float*>(&r);
#pragma unroll
    for (int j = 0; j < 4; j++) {
        int c = c0 + j;
        float s = __ldg(g + c) * rsqrtf(__ldg(rv + c) + 1e-5f);
        float t = (o[j] + __ldg(b + c) - __ldg(rm + c)) * s + __ldg(be + c);
        rr[j] = elu1(t);
    }
    reinterpret_cast<float4*>(h)[i] = r;
}

__global__ void final_kernel(const float* __restrict__ h2, const float* __restrict__ acc3,
                             const float* __restrict__ b, const float* __restrict__ g,
                             const float* __restrict__ be, const float* __restrict__ rm,
                             const float* __restrict__ rv, float* __restrict__ out) {
    int i = blockIdx.x * blockDim.x + threadIdx.x;
    if (i >= NNODES * COUT / 4) return;
    float4 a = reinterpret_cast<const float4*>(h2)[i];
    float4 c4 = reinterpret_cast<const float4*>(acc3)[i];
    int c0 = (i * 4) & (COUT - 1);
    float o[4] = {a.x + c4.x, a.y + c4.y, a.z + c4.z, a.w + c4.w};
    float4 r;
    float* rr = reinterpret_cast<float*>(&r);
#pragma unroll
    for (int j = 0; j < 4; j++) {
        int c = c0 + j;
        float s = __ldg(g + c) * rsqrtf(__ldg(rv + c) + 1e-5f);
        float t = (o[j] + __ldg(b + c) - __ldg(rm + c)) * s + __ldg(be + c);
        rr[j] = elu1(t);
    }
    reinterpret_cast<float4*>(out)[i] = r;
}

// ---------------- launch ----------------
extern "C" void kernel_launch(void* const* d_in, const int* in_sizes, int n_in,
                              void* d_out, int out_size) {
    const float* x   = (const float*)d_in[0];
    const int*   ei  = (const int*)d_in[1];
    const int*   sel = (const int*)d_in[2];
    const float* W1  = (const float*)d_in[3];
    const float* b1  = (const float*)d_in[4];
    const float* g1  = (const float*)d_in[5];
    const float* be1 = (const float*)d_in[6];
    const float* rm1 = (const float*)d_in[7];
    const float* rv1 = (const float*)d_in[8];
    const float* W2  = (const float*)d_in[9];
    const float* b2  = (const float*)d_in[10];
    const float* g2  = (const float*)d_in[11];
    const float* be2 = (const float*)d_in[12];
    const float* rm2 = (const float*)d_in[13];
    const float* rv2 = (const float*)d_in[14];
    const float* W3  = (const float*)d_in[15];
    const float* b3  = (const float*)d_in[16];
    const float* g3  = (const float*)d_in[17];
    const float* be3 = (const float*)d_in[18];
    const float* rm3 = (const float*)d_in[19];
    const float* rv3 = (const float*)d_in[20];
    float* out = (float*)d_out;

    const int E = in_sizes[2];
    const int* src = ei;
    const int* dst = ei + E;

    float *acc, *acc3, *h1, *h2;
    __half *Abx, *Abh, *Wb1, *Wb2, *Wb3;
    int *cnt, *boffs, *cur;
    uint32_t *ebuf;
    cudaGetSymbolAddress((void**)&acc, g_acc);
    cudaGetSymbolAddress((void**)&acc3, g_acc3);
    cudaGetSymbolAddress((void**)&h1, g_h1);
    cudaGetSymbolAddress((void**)&h2, g_h2);
    cudaGetSymbolAddress((void**)&Abx, g_Abx);
    cudaGetSymbolAddress((void**)&Abh, g_Abh);
    cudaGetSymbolAddress((void**)&Wb1, g_Wb1);
    cudaGetSymbolAddress((void**)&Wb2, g_Wb2);
    cudaGetSymbolAddress((void**)&Wb3, g_Wb3);
    cudaGetSymbolAddress((void**)&cnt, g_cnt);
    cudaGetSymbolAddress((void**)&boffs, g_boffs);
    cudaGetSymbolAddress((void**)&cur, g_cur);
    cudaGetSymbolAddress((void**)&ebuf, g_ebuf);

    cudaFuncSetAttribute(gemm_scatter_kernel,
                         cudaFuncAttributeMaxDynamicSharedMemorySize, SMEM_BYTES);

    const size_t accBytes = (size_t)NNODES * COUT * sizeof(float);
    const int nc4 = NNODES * COUT / 4;
    const int ew_blocks = (nc4 + 255) / 256;
    const int prepA_blocks = (NNODES * 32 + 255) / 256;
    const int prepW9_blocks = (NDIR * CIN * COUT + 255) / 256;
    const int prepW1_blocks = (CIN * COUT + 255) / 256;
    const int e_blocks = (E + 255) / 256;

    // ---- prep + bucketing ----
    cudaMemsetAsync(cnt, 0, NBUCK * sizeof(int));
    prepW_kernel<<<prepW9_blocks, 256>>>(W1, Wb1, NDIR * CIN * COUT);
    prepW_kernel<<<prepW9_blocks, 256>>>(W2, Wb2, NDIR * CIN * COUT);
    prepW_kernel<<<prepW1_blocks, 256>>>(W3, Wb3, CIN * COUT);
    prepA_kernel<<<prepA_blocks, 256>>>(x, Abx);
    hist_kernel<<<e_blocks, 256>>>(src, sel, cnt, E);
    scan_kernel<<<1, 256>>>(cnt, boffs, cur);
    fill_kernel<<<e_blocks, 256>>>(src, dst, sel, cur, ebuf, E);

    cudaMemsetAsync(acc, 0, accBytes);
    cudaMemsetAsync(acc3, 0, accBytes);

    // ---- layer 1 (9-dir) + shortcut (dir 0 only) ----
    gemm_scatter_kernel<<<dim3(NDIR, NTILES), 256, SMEM_BYTES>>>(Abx, Wb1, boffs, ebuf, acc);
    gemm_scatter_kernel<<<dim3(1, NTILES), 256, SMEM_BYTES>>>(Abx, Wb3, boffs, ebuf, acc3);
    bnelu_kernel<<<ew_blocks, 256>>>(acc, b1, g1, be1, rm1, rv1, h1);

    // ---- layer 2 (9-dir) ----
    prepA_kernel<<<prepA_blocks, 256>>>(h1, Abh);
    cudaMemsetAsync(acc, 0, accBytes);
    gemm_scatter_kernel<<<dim3(NDIR, NTILES), 256, SMEM_BYTES>>>(Abh, Wb2, boffs, ebuf, acc);
    bnelu_kernel<<<ew_blocks, 256>>>(acc, b2, g2, be2, rm2, rv2, h2);

    // ---- combine: ELU(BN3(h2 + sc)) ----
    final_kernel<<<ew_blocks, 256>>>(h2, acc3, b3, g3, be3, rm3, rv3, out);
}

// round 5
// speedup vs baseline: 3.5914x; 1.2604x over previous
#include <cuda_runtime.h>
#include <cuda_fp16.h>
#include <cstdint>
#include <cstddef>

#define NNODES 65536
#define CIN    128
#define COUT   128
#define NDIR   9
#define NTILES (NNODES / 128)        // 512
#define NBUCK  (NTILES * NDIR)       // 4608
#define EMAX   1048576

// ---------------- scratch (static device globals; no allocation) ----------------
__device__ __align__(256) float g_acc[(size_t)NNODES * COUT];
__device__ __align__(256) float g_acc3[(size_t)NNODES * COUT];
__device__ __align__(256) float g_h2[(size_t)NNODES * COUT];
__device__ __align__(256) __half g_Abx[(size_t)NNODES * 128]; // fp16 features
__device__ __align__(256) __half g_Abh[(size_t)NNODES * 128];
__device__ __align__(256) __half g_Wb1[(size_t)NDIR * 128 * 128]; // [d*128+c][k]
__device__ __align__(256) __half g_Wb2[(size_t)NDIR * 128 * 128];
__device__ __align__(256) __half g_Wb3[(size_t)128 * 128];
__device__ int g_cnt[NBUCK];
__device__ int g_boffs[NBUCK + 1];
__device__ int g_cur[NBUCK];
__device__ uint32_t g_ebuf[EMAX];    // packed: dst[0:16) | localsrc[16:23)

// ---------------- PTX helpers ----------------
__device__ __forceinline__ uint32_t smem_u32(const void* p) {
    uint32_t a;
    asm("{ .reg .u64 t; cvta.to.shared.u64 t, %1; cvt.u32.u64 %0, t; }" : "=r"(a) : "l"(p));
    return a;
}
__device__ __forceinline__ void cp_async16(uint32_t saddr, const void* gptr) {
    asm volatile("cp.async.cg.shared.global [%0], [%1], 16;" :: "r"(saddr), "l"(gptr) : "memory");
}
__device__ __forceinline__ void cp_commit() {
    asm volatile("cp.async.commit_group;" ::: "memory");
}
template <int N>
__device__ __forceinline__ void cp_wait() {
    asm volatile("cp.async.wait_group %0;" :: "n"(N) : "memory");
}
__device__ __forceinline__ void ldsm_x4(uint32_t* r, uint32_t addr) {
    asm volatile("ldmatrix.sync.aligned.m8n8.x4.shared.b16 {%0,%1,%2,%3}, [%4];"
                 : "=r"(r[0]), "=r"(r[1]), "=r"(r[2]), "=r"(r[3]) : "r"(addr));
}
__device__ __forceinline__ void mma16816(float* d, const uint32_t* a, const uint32_t* b) {
    asm volatile(
        "mma.sync.aligned.m16n8k16.row.col.f32.f16.f16.f32 "
        "{%0,%1,%2,%3}, {%4,%5,%6,%7}, {%8,%9}, {%0,%1,%2,%3};"
        : "+f"(d[0]), "+f"(d[1]), "+f"(d[2]), "+f"(d[3])
        : "r"(a[0]), "r"(a[1]), "r"(a[2]), "r"(a[3]), "r"(b[0]), "r"(b[1]));
}

// SMEM layout (dynamic, 1024-aligned base):
//   [0, 16K)      A chunk 0 (K 0..63)
//   [16K, 32K)    A chunk 1 (K 64..127)
//   [32K, 48K)    B chunk 0
//   [48K, 64K)    B chunk 1
//   after mainloop, the region is reused as Y tile: float[128][132]
static constexpr int YSTRIDE = 132;
static constexpr int SMEM_BYTES = 1024 + 128 * YSTRIDE * 4;  // 68608

// ---------------- fused GEMM + scatter ----------------
// grid = (nd, 512). CTA computes Y tile [128 nodes x 128 cols] for direction blockIdx.x
// (single-term fp16, K=128), then scatters bucket edges into gacc.
__global__ void __launch_bounds__(256, 2)
gemm_scatter_kernel(const __half* __restrict__ Ab,   // [N][128] fp16
                    const __half* __restrict__ Bb,   // [nd*128][128] fp16, k contiguous
                    const int* __restrict__ boffs,
                    const uint32_t* __restrict__ ebuf,
                    float* __restrict__ gacc)
{
    extern __shared__ char smem_raw[];
    char* sdata = (char*)(((uintptr_t)smem_raw + 1023) & ~(uintptr_t)1023);
    const uint32_t sb = smem_u32(sdata);

    const int tid = threadIdx.x;
    const int wid = tid >> 5, lane = tid & 31;
    const int warpM = wid & 1;
    const int warpN = wid >> 1;
    const int rowBase = blockIdx.y << 7;
    const int colBase = blockIdx.x << 7;   // weight row block (direction*128)
    const int bucket = blockIdx.y * NDIR + blockIdx.x;

    float cfrag[4][4][4];
#pragma unroll
    for (int mt = 0; mt < 4; mt++)
#pragma unroll
        for (int nt = 0; nt < 4; nt++)
#pragma unroll
            for (int j = 0; j < 4; j++) cfrag[mt][nt][j] = 0.f;

    auto load_A = [&](int c) {
        uint32_t aBase = sb + (uint32_t)c * 16384;
#pragma unroll
        for (int i = 0; i < 4; i++) {
            int idx = tid + (i << 8);          // 0..1023
            int row = idx >> 3, g = idx & 7;
            uint32_t so = (uint32_t)row * 128 + (uint32_t)((g ^ (row & 7)) << 4);
            cp_async16(aBase + so, Ab + (size_t)(rowBase + row) * 128 + c * 64 + g * 8);
        }
    };
    auto load_B = [&]() {
#pragma unroll
        for (int i = 0; i < 8; i++) {
            int idx = tid + (i << 8);          // 0..2047
            int ch = idx >> 10;                // chunk 0/1
            int row = (idx >> 3) & 127, g = idx & 7;
            uint32_t so = 32768u + (uint32_t)ch * 16384 + (uint32_t)row * 128
                        + (uint32_t)((g ^ (row & 7)) << 4);
            cp_async16(sb + so, Bb + (size_t)(colBase + row) * 128 + ch * 64 + g * 8);
        }
    };

    load_B();
    load_A(0);
    cp_commit();
    load_A(1);
    cp_commit();

#pragma unroll
    for (int c = 0; c < 2; c++) {
        if (c == 0) cp_wait<1>();
        else        cp_wait<0>();
        __syncthreads();

        uint32_t aBase = sb + (uint32_t)c * 16384;
        uint32_t bBase = sb + 32768u + (uint32_t)c * 16384;

#pragma unroll
        for (int ks = 0; ks < 4; ks++) {
            uint32_t aF[4][4];
#pragma unroll
            for (int mt = 0; mt < 4; mt++) {
                int row = warpM * 64 + mt * 16 + (lane & 15);
                int g = ks * 2 + (lane >> 4);
                ldsm_x4(aF[mt], aBase + (uint32_t)row * 128 + (uint32_t)((g ^ (row & 7)) << 4));
            }
            uint32_t bF[4][2];
#pragma unroll
            for (int p = 0; p < 2; p++) {
                int n = warpN * 32 + p * 16 + ((lane >> 4) << 3) + (lane & 7);
                int g = ks * 2 + ((lane >> 3) & 1);
                uint32_t r[4];
                ldsm_x4(r, bBase + (uint32_t)n * 128 + (uint32_t)((g ^ (n & 7)) << 4));
                bF[2 * p][0] = r[0]; bF[2 * p][1] = r[1];
                bF[2 * p + 1][0] = r[2]; bF[2 * p + 1][1] = r[3];
            }
#pragma unroll
            for (int mt = 0; mt < 4; mt++)
#pragma unroll
                for (int nt = 0; nt < 4; nt++)
                    mma16816(cfrag[mt][nt], aF[mt], bF[nt]);
        }
    }
    __syncthreads();   // all ldsm reads done before Y-tile overwrite

    // ---- write Y tile to SMEM (reuse pipeline region) ----
    float* yt = reinterpret_cast<float*>(sdata);
#pragma unroll
    for (int mt = 0; mt < 4; mt++) {
        int r0 = warpM * 64 + mt * 16 + (lane >> 2);
#pragma unroll
        for (int nt = 0; nt < 4; nt++) {
            int c0 = warpN * 32 + nt * 8 + ((lane & 3) << 1);
            yt[r0 * YSTRIDE + c0]       = cfrag[mt][nt][0];
            yt[r0 * YSTRIDE + c0 + 1]   = cfrag[mt][nt][1];
            yt[(r0 + 8) * YSTRIDE + c0]     = cfrag[mt][nt][2];
            yt[(r0 + 8) * YSTRIDE + c0 + 1] = cfrag[mt][nt][3];
        }
    }
    __syncthreads();

    // ---- scatter this bucket's edges ----
    const int e0 = __ldg(boffs + bucket);
    const int e1 = __ldg(boffs + bucket + 1);
    for (int e = e0 + wid; e < e1; e += 8) {
        uint32_t pk = __ldg(ebuf + e);
        int ls = pk >> 16;             // local src row (0..127)
        int dst = pk & 0xFFFF;
        float4 v = *reinterpret_cast<const float4*>(yt + (size_t)ls * YSTRIDE + lane * 4);
        float* op = gacc + (size_t)dst * COUT + lane * 4;
        asm volatile("red.global.add.v4.f32 [%0], {%1,%2,%3,%4};"
                     :: "l"(op), "f"(v.x), "f"(v.y), "f"(v.z), "f"(v.w)
                     : "memory");
    }
}

// ---------------- edge bucketing ----------------
__global__ void hist_kernel(const int* __restrict__ src, const int* __restrict__ sel,
                            int* __restrict__ cnt, int E) {
    int i = blockIdx.x * blockDim.x + threadIdx.x;
    if (i >= E) return;
    int b = (__ldg(src + i) >> 7) * NDIR + __ldg(sel + i);
    atomicAdd(cnt + b, 1);
}

__global__ void scan_kernel(const int* __restrict__ cnt, int* __restrict__ boffs,
                            int* __restrict__ cur) {
    __shared__ int part[256];
    __shared__ int partpf[257];
    const int PER = NBUCK / 256;   // 18
    int t = threadIdx.x;
    int base = t * PER;
    int loc[PER];
    int s = 0;
#pragma unroll
    for (int j = 0; j < PER; j++) { loc[j] = s; s += cnt[base + j]; }
    part[t] = s;
    __syncthreads();
    if (t == 0) {
        int r = 0;
        for (int i = 0; i < 256; i++) { partpf[i] = r; r += part[i]; }
        partpf[256] = r;
    }
    __syncthreads();
    int off = partpf[t];
#pragma unroll
    for (int j = 0; j < PER; j++) {
        int v = off + loc[j];
        boffs[base + j] = v;
        cur[base + j] = v;
    }
    if (t == 255) boffs[NBUCK] = partpf[256];
}

__global__ void fill_kernel(const int* __restrict__ src, const int* __restrict__ dst,
                            const int* __restrict__ sel, int* __restrict__ cur,
                            uint32_t* __restrict__ ebuf, int E) {
    int i = blockIdx.x * blockDim.x + threadIdx.x;
    if (i >= E) return;
    int s = __ldg(src + i);
    int b = (s >> 7) * NDIR + __ldg(sel + i);
    int p = atomicAdd(cur + b, 1);
    ebuf[p] = (uint32_t)(__ldg(dst + i) & 0xFFFF) | ((uint32_t)(s & 127) << 16);
}

// ---------------- prep kernels ----------------
// X fp32 [N][128] -> fp16 [N][128]
__global__ void prepA_kernel(const float* __restrict__ X, __half* __restrict__ Ah) {
    int i = blockIdx.x * blockDim.x + threadIdx.x;   // over N*32 float4s
    if (i >= NNODES * 32) return;
    float4 x = reinterpret_cast<const float4*>(X)[i];
    __half2 p0 = __halves2half2(__float2half_rn(x.x), __float2half_rn(x.y));
    __half2 p1 = __halves2half2(__float2half_rn(x.z), __float2half_rn(x.w));
    reinterpret_cast<__half2*>(Ah)[i * 2]     = p0;
    reinterpret_cast<__half2*>(Ah)[i * 2 + 1] = p1;
}

// W fp32 [d][k][c] -> Wb fp16 [(d*128+c)][k]
__global__ void prepW_kernel(const float* __restrict__ W, __half* __restrict__ Wb, int total) {
    int idx = blockIdx.x * blockDim.x + threadIdx.x;
    if (idx >= total) return;
    int d = idx >> 14;
    int k = (idx >> 7) & 127;
    int c = idx & 127;
    Wb[((size_t)d * 128 + c) * 128 + k] = __float2half_rn(W[idx]);
}

// ---------------- fused bias + BN(eval) + ELU ----------------
__device__ __forceinline__ float elu1(float t) { return t > 0.f ? t : expm1f(t); }

// layer-1 variant: output consumed only by the next GEMM -> write fp16 directly
__global__ void bnelu_prep_kernel(const float* __restrict__ acc, const float* __restrict__ b,
                                  const float* __restrict__ g, const float* __restrict__ be,
                                  const float* __restrict__ rm, const float* __restrict__ rv,
                                  __half* __restrict__ Ah) {
    int i = blockIdx.x * blockDim.x + threadIdx.x;
    if (i >= NNODES * COUT / 4) return;
    float4 v = reinterpret_cast<const float4*>(acc)[i];
    int c0 = (i * 4) & (COUT - 1);
    float o[4] = {v.x, v.y, v.z, v.w};
    float rr[4];
#pragma unroll
    for (int j = 0; j < 4; j++) {
        int c = c0 + j;
        float s = __ldg(g + c) * rsqrtf(__ldg(rv + c) + 1e-5f);
        float t = (o[j] + __ldg(b + c) - __ldg(rm + c)) * s + __ldg(be + c);
        rr[j] = elu1(t);
    }
    reinterpret_cast<__half2*>(Ah)[i * 2] =
        __halves2half2(__float2half_rn(rr[0]), __float2half_rn(rr[1]));
    reinterpret_cast<__half2*>(Ah)[i * 2 + 1] =
        __halves2half2(__float2half_rn(rr[2]), __float2half_rn(rr[3]));
}

__global__ void bnelu_kernel(const float* __restrict__ acc, const float* __restrict__ b,
                             const float* __restrict__ g, const float* __restrict__ be,
                             const float* __restrict__ rm, const float* __restrict__ rv,
                             float* __restrict__ h) {
    int i = blockIdx.x * blockDim.x + threadIdx.x;
    if (i >= NNODES * COUT / 4) return;
    float4 v = reinterpret_cast<const float4*>(acc)[i];
    int c0 = (i * 4) & (COUT - 1);
    float o[4] = {v.x, v.y, v.z, v.w};
    float4 r;
    float* rr = reinterpret_cast<float*>(&r);
#pragma unroll
    for (int j = 0; j < 4; j++) {
        int c = c0 + j;
        float s = __ldg(g + c) * rsqrtf(__ldg(rv + c) + 1e-5f);
        float t = (o[j] + __ldg(b + c) - __ldg(rm + c)) * s + __ldg(be + c);
        rr[j] = elu1(t);
    }
    reinterpret_cast<float4*>(h)[i] = r;
}

__global__ void final_kernel(const float* __restrict__ h2, const float* __restrict__ acc3,
                             const float* __restrict__ b, const float* __restrict__ g,
                             const float* __restrict__ be, const float* __restrict__ rm,
                             const float* __restrict__ rv, float* __restrict__ out) {
    int i = blockIdx.x * blockDim.x + threadIdx.x;
    if (i >= NNODES * COUT / 4) return;
    float4 a = reinterpret_cast<const float4*>(h2)[i];
    float4 c4 = reinterpret_cast<const float4*>(acc3)[i];
    int c0 = (i * 4) & (COUT - 1);
    float o[4] = {a.x + c4.x, a.y + c4.y, a.z + c4.z, a.w + c4.w};
    float4 r;
    float* rr = reinterpret_cast<float*>(&r);
#pragma unroll
    for (int j = 0; j < 4; j++) {
        int c = c0 + j;
        float s = __ldg(g + c) * rsqrtf(__ldg(rv + c) + 1e-5f);
        float t = (o[j] + __ldg(b + c) - __ldg(rm + c)) * s + __ldg(be + c);
        rr[j] = elu1(t);
    }
    reinterpret_cast<float4*>(out)[i] = r;
}

// ---------------- launch ----------------
extern "C" void kernel_launch(void* const* d_in, const int* in_sizes, int n_in,
                              void* d_out, int out_size) {
    const float* x   = (const float*)d_in[0];
    const int*   ei  = (const int*)d_in[1];
    const int*   sel = (const int*)d_in[2];
    const float* W1  = (const float*)d_in[3];
    const float* b1  = (const float*)d_in[4];
    const float* g1  = (const float*)d_in[5];
    const float* be1 = (const float*)d_in[6];
    const float* rm1 = (const float*)d_in[7];
    const float* rv1 = (const float*)d_in[8];
    const float* W2  = (const float*)d_in[9];
    const float* b2  = (const float*)d_in[10];
    const float* g2  = (const float*)d_in[11];
    const float* be2 = (const float*)d_in[12];
    const float* rm2 = (const float*)d_in[13];
    const float* rv2 = (const float*)d_in[14];
    const float* W3  = (const float*)d_in[15];
    const float* b3  = (const float*)d_in[16];
    const float* g3  = (const float*)d_in[17];
    const float* be3 = (const float*)d_in[18];
    const float* rm3 = (const float*)d_in[19];
    const float* rv3 = (const float*)d_in[20];
    float* out = (float*)d_out;

    const int E = in_sizes[2];
    const int* src = ei;
    const int* dst = ei + E;

    float *acc, *acc3, *h2;
    __half *Abx, *Abh, *Wb1, *Wb2, *Wb3;
    int *cnt, *boffs, *cur;
    uint32_t *ebuf;
    cudaGetSymbolAddress((void**)&acc, g_acc);
    cudaGetSymbolAddress((void**)&acc3, g_acc3);
    cudaGetSymbolAddress((void**)&h2, g_h2);
    cudaGetSymbolAddress((void**)&Abx, g_Abx);
    cudaGetSymbolAddress((void**)&Abh, g_Abh);
    cudaGetSymbolAddress((void**)&Wb1, g_Wb1);
    cudaGetSymbolAddress((void**)&Wb2, g_Wb2);
    cudaGetSymbolAddress((void**)&Wb3, g_Wb3);
    cudaGetSymbolAddress((void**)&cnt, g_cnt);
    cudaGetSymbolAddress((void**)&boffs, g_boffs);
    cudaGetSymbolAddress((void**)&cur, g_cur);
    cudaGetSymbolAddress((void**)&ebuf, g_ebuf);

    cudaFuncSetAttribute(gemm_scatter_kernel,
                         cudaFuncAttributeMaxDynamicSharedMemorySize, SMEM_BYTES);

    const size_t accBytes = (size_t)NNODES * COUT * sizeof(float);
    const int nc4 = NNODES * COUT / 4;
    const int ew_blocks = (nc4 + 255) / 256;
    const int prepA_blocks = (NNODES * 32 + 255) / 256;
    const int prepW9_blocks = (NDIR * CIN * COUT + 255) / 256;
    const int prepW1_blocks = (CIN * COUT + 255) / 256;
    const int e_blocks = (E + 255) / 256;

    // ---- prep + bucketing ----
    cudaMemsetAsync(cnt, 0, NBUCK * sizeof(int));
    prepW_kernel<<<prepW9_blocks, 256>>>(W1, Wb1, NDIR * CIN * COUT);
    prepW_kernel<<<prepW9_blocks, 256>>>(W2, Wb2, NDIR * CIN * COUT);
    prepW_kernel<<<prepW1_blocks, 256>>>(W3, Wb3, CIN * COUT);
    prepA_kernel<<<prepA_blocks, 256>>>(x, Abx);
    hist_kernel<<<e_blocks, 256>>>(src, sel, cnt, E);
    scan_kernel<<<1, 256>>>(cnt, boffs, cur);
    fill_kernel<<<e_blocks, 256>>>(src, dst, sel, cur, ebuf, E);

    cudaMemsetAsync(acc, 0, accBytes);
    cudaMemsetAsync(acc3, 0, accBytes);

    // ---- layer 1 (9-dir) + shortcut (dir 0 only) ----
    gemm_scatter_kernel<<<dim3(NDIR, NTILES), 256, SMEM_BYTES>>>(Abx, Wb1, boffs, ebuf, acc);
    gemm_scatter_kernel<<<dim3(1, NTILES), 256, SMEM_BYTES>>>(Abx, Wb3, boffs, ebuf, acc3);
    bnelu_prep_kernel<<<ew_blocks, 256>>>(acc, b1, g1, be1, rm1, rv1, Abh);

    // ---- layer 2 (9-dir) ----
    cudaMemsetAsync(acc, 0, accBytes);
    gemm_scatter_kernel<<<dim3(NDIR, NTILES), 256, SMEM_BYTES>>>(Abh, Wb2, boffs, ebuf, acc);
    bnelu_kernel<<<ew_blocks, 256>>>(acc, b2, g2, be2, rm2, rv2, h2);

    // ---- combine: ELU(BN3(h2 + sc)) ----
    final_kernel<<<ew_blocks, 256>>>(h2, acc3, b3, g3, be3, rm3, rv3, out);
}

// round 6
// speedup vs baseline: 3.9217x; 1.0920x over previous
#include <cuda_runtime.h>
#include <cuda_fp16.h>
#include <cstdint>
#include <cstddef>

#define NNODES 65536
#define CIN    128
#define COUT   128
#define NDIR   9
#define NTILES (NNODES / 128)        // 512
#define NBUCK  (NTILES * NDIR)       // 4608
#define EMAX   1048576

// ---------------- scratch (static device globals; no allocation) ----------------
__device__ __align__(256) float g_acc[(size_t)NNODES * COUT];
__device__ __align__(256) float g_acc3[(size_t)NNODES * COUT];
__device__ __align__(256) __half g_Abx[(size_t)NNODES * 128]; // fp16 features
__device__ __align__(256) __half g_Abh[(size_t)NNODES * 128];
__device__ __align__(256) __half g_WbA[(size_t)(NDIR + 1) * 128 * 128]; // W1 dirs 0-8, W3 as dir 9
__device__ __align__(256) __half g_Wb2[(size_t)NDIR * 128 * 128];
__device__ int g_cnt[NBUCK];
__device__ int g_boffs[NBUCK + 1];
__device__ int g_cur[NBUCK];
__device__ uint32_t g_ebuf[EMAX];    // packed: dst[0:16) | localsrc[16:23)

// ---------------- PTX helpers ----------------
__device__ __forceinline__ uint32_t smem_u32(const void* p) {
    uint32_t a;
    asm("{ .reg .u64 t; cvta.to.shared.u64 t, %1; cvt.u32.u64 %0, t; }" : "=r"(a) : "l"(p));
    return a;
}
__device__ __forceinline__ void cp_async16(uint32_t saddr, const void* gptr) {
    asm volatile("cp.async.cg.shared.global [%0], [%1], 16;" :: "r"(saddr), "l"(gptr) : "memory");
}
__device__ __forceinline__ void cp_commit() {
    asm volatile("cp.async.commit_group;" ::: "memory");
}
template <int N>
__device__ __forceinline__ void cp_wait() {
    asm volatile("cp.async.wait_group %0;" :: "n"(N) : "memory");
}
__device__ __forceinline__ void ldsm_x4(uint32_t* r, uint32_t addr) {
    asm volatile("ldmatrix.sync.aligned.m8n8.x4.shared.b16 {%0,%1,%2,%3}, [%4];"
                 : "=r"(r[0]), "=r"(r[1]), "=r"(r[2]), "=r"(r[3]) : "r"(addr));
}
__device__ __forceinline__ void mma16816(float* d, const uint32_t* a, const uint32_t* b) {
    asm volatile(
        "mma.sync.aligned.m16n8k16.row.col.f32.f16.f16.f32 "
        "{%0,%1,%2,%3}, {%4,%5,%6,%7}, {%8,%9}, {%0,%1,%2,%3};"
        : "+f"(d[0]), "+f"(d[1]), "+f"(d[2]), "+f"(d[3])
        : "r"(a[0]), "r"(a[1]), "r"(a[2]), "r"(a[3]), "r"(b[0]), "r"(b[1]));
}

// SMEM layout (dynamic, 1024-aligned base):
//   [0, 16K)  A chunk0 | [16K,32K) A chunk1 | [32K,48K) B chunk0 | [48K,64K) B chunk1
//   after mainloop, region reused as Y tile: float[128][132]
static constexpr int YSTRIDE = 132;
static constexpr int SMEM_BYTES = 1024 + 128 * YSTRIDE * 4;  // 68608

// ---------------- fused GEMM + scatter ----------------
// grid = (ndirs, 512). CTA computes Y tile [128 nodes x 128 cols] for weight block
// blockIdx.x (K=128 fp16), then scatters bucket edges into the accumulator.
// WITH_SC: blockIdx.x == NDIR means shortcut (W3): bucket dir 0, target acc3.
template <bool WITH_SC>
__global__ void __launch_bounds__(256, 2)
gemm_scatter_kernel(const __half* __restrict__ Ab,   // [N][128] fp16
                    const __half* __restrict__ Bb,   // [(ndirs)*128][128] fp16, k contiguous
                    const int* __restrict__ boffs,
                    const uint32_t* __restrict__ ebuf,
                    float* __restrict__ gacc,
                    float* __restrict__ gacc3)
{
    extern __shared__ char smem_raw[];
    char* sdata = (char*)(((uintptr_t)smem_raw + 1023) & ~(uintptr_t)1023);
    const uint32_t sb = smem_u32(sdata);

    const int tid = threadIdx.x;
    const int wid = tid >> 5, lane = tid & 31;
    const int warpM = wid & 1;
    const int warpN = wid >> 1;
    const int rowBase = blockIdx.y << 7;
    const int colBase = blockIdx.x << 7;   // weight row block
    const bool sc = WITH_SC && (blockIdx.x == NDIR);
    const int bdir = sc ? 0 : blockIdx.x;
    const int bucket = blockIdx.y * NDIR + bdir;
    float* target = sc ? gacc3 : gacc;

    float cfrag[4][4][4];
#pragma unroll
    for (int mt = 0; mt < 4; mt++)
#pragma unroll
        for (int nt = 0; nt < 4; nt++)
#pragma unroll
            for (int j = 0; j < 4; j++) cfrag[mt][nt][j] = 0.f;

    auto load_A = [&](int c) {
        uint32_t aBase = sb + (uint32_t)c * 16384;
#pragma unroll
        for (int i = 0; i < 4; i++) {
            int idx = tid + (i << 8);          // 0..1023
            int row = idx >> 3, g = idx & 7;
            uint32_t so = (uint32_t)row * 128 + (uint32_t)((g ^ (row & 7)) << 4);
            cp_async16(aBase + so, Ab + (size_t)(rowBase + row) * 128 + c * 64 + g * 8);
        }
    };
    auto load_B = [&]() {
#pragma unroll
        for (int i = 0; i < 8; i++) {
            int idx = tid + (i << 8);          // 0..2047
            int ch = idx >> 10;                // chunk 0/1
            int row = (idx >> 3) & 127, g = idx & 7;
            uint32_t so = 32768u + (uint32_t)ch * 16384 + (uint32_t)row * 128
                        + (uint32_t)((g ^ (row & 7)) << 4);
            cp_async16(sb + so, Bb + (size_t)(colBase + row) * 128 + ch * 64 + g * 8);
        }
    };

    load_B();
    load_A(0);
    cp_commit();
    load_A(1);
    cp_commit();

#pragma unroll
    for (int c = 0; c < 2; c++) {
        if (c == 0) cp_wait<1>();
        else        cp_wait<0>();
        __syncthreads();

        uint32_t aBase = sb + (uint32_t)c * 16384;
        uint32_t bBase = sb + 32768u + (uint32_t)c * 16384;

#pragma unroll
        for (int ks = 0; ks < 4; ks++) {
            uint32_t aF[4][4];
#pragma unroll
            for (int mt = 0; mt < 4; mt++) {
                int row = warpM * 64 + mt * 16 + (lane & 15);
                int g = ks * 2 + (lane >> 4);
                ldsm_x4(aF[mt], aBase + (uint32_t)row * 128 + (uint32_t)((g ^ (row & 7)) << 4));
            }
            uint32_t bF[4][2];
#pragma unroll
            for (int p = 0; p < 2; p++) {
                int n = warpN * 32 + p * 16 + ((lane >> 4) << 3) + (lane & 7);
                int g = ks * 2 + ((lane >> 3) & 1);
                uint32_t r[4];
                ldsm_x4(r, bBase + (uint32_t)n * 128 + (uint32_t)((g ^ (n & 7)) << 4));
                bF[2 * p][0] = r[0]; bF[2 * p][1] = r[1];
                bF[2 * p + 1][0] = r[2]; bF[2 * p + 1][1] = r[3];
            }
#pragma unroll
            for (int mt = 0; mt < 4; mt++)
#pragma unroll
                for (int nt = 0; nt < 4; nt++)
                    mma16816(cfrag[mt][nt], aF[mt], bF[nt]);
        }
    }
    __syncthreads();   // all ldsm reads done before Y-tile overwrite

    // ---- write Y tile to SMEM (reuse pipeline region) ----
    float* yt = reinterpret_cast<float*>(sdata);
#pragma unroll
    for (int mt = 0; mt < 4; mt++) {
        int r0 = warpM * 64 + mt * 16 + (lane >> 2);
#pragma unroll
        for (int nt = 0; nt < 4; nt++) {
            int c0 = warpN * 32 + nt * 8 + ((lane & 3) << 1);
            yt[r0 * YSTRIDE + c0]       = cfrag[mt][nt][0];
            yt[r0 * YSTRIDE + c0 + 1]   = cfrag[mt][nt][1];
            yt[(r0 + 8) * YSTRIDE + c0]     = cfrag[mt][nt][2];
            yt[(r0 + 8) * YSTRIDE + c0 + 1] = cfrag[mt][nt][3];
        }
    }
    __syncthreads();

    // ---- scatter this bucket's edges ----
    const int e0 = __ldg(boffs + bucket);
    const int e1 = __ldg(boffs + bucket + 1);
    for (int e = e0 + wid; e < e1; e += 8) {
        uint32_t pk = __ldg(ebuf + e);
        int ls = pk >> 16;             // local src row (0..127)
        int dst = pk & 0xFFFF;
        float4 v = *reinterpret_cast<const float4*>(yt + (size_t)ls * YSTRIDE + lane * 4);
        float* op = target + (size_t)dst * COUT + lane * 4;
        asm volatile("red.global.add.v4.f32 [%0], {%1,%2,%3,%4};"
                     :: "l"(op), "f"(v.x), "f"(v.y), "f"(v.z), "f"(v.w)
                     : "memory");
    }
}

// ---------------- edge bucketing ----------------
__global__ void hist_kernel(const int* __restrict__ src, const int* __restrict__ sel,
                            int* __restrict__ cnt, int E) {
    int i = blockIdx.x * blockDim.x + threadIdx.x;
    if (i >= E) return;
    int b = (__ldg(src + i) >> 7) * NDIR + __ldg(sel + i);
    atomicAdd(cnt + b, 1);
}

__global__ void scan_kernel(const int* __restrict__ cnt, int* __restrict__ boffs,
                            int* __restrict__ cur) {
    __shared__ int part[256];
    __shared__ int partpf[257];
    const int PER = NBUCK / 256;   // 18
    int t = threadIdx.x;
    int base = t * PER;
    int loc[PER];
    int s = 0;
#pragma unroll
    for (int j = 0; j < PER; j++) { loc[j] = s; s += cnt[base + j]; }
    part[t] = s;
    __syncthreads();
    if (t == 0) {
        int r = 0;
        for (int i = 0; i < 256; i++) { partpf[i] = r; r += part[i]; }
        partpf[256] = r;
    }
    __syncthreads();
    int off = partpf[t];
#pragma unroll
    for (int j = 0; j < PER; j++) {
        int v = off + loc[j];
        boffs[base + j] = v;
        cur[base + j] = v;
    }
    if (t == 255) boffs[NBUCK] = partpf[256];
}

__global__ void fill_kernel(const int* __restrict__ src, const int* __restrict__ dst,
                            const int* __restrict__ sel, int* __restrict__ cur,
                            uint32_t* __restrict__ ebuf, int E) {
    int i = blockIdx.x * blockDim.x + threadIdx.x;
    if (i >= E) return;
    int s = __ldg(src + i);
    int b = (s >> 7) * NDIR + __ldg(sel + i);
    int p = atomicAdd(cur + b, 1);
    ebuf[p] = (uint32_t)(__ldg(dst + i) & 0xFFFF) | ((uint32_t)(s & 127) << 16);
}

// ---------------- prep kernels ----------------
// zero both accumulators in one pass
__global__ void zero_both_kernel(float* __restrict__ a, float* __restrict__ b) {
    int i = blockIdx.x * blockDim.x + threadIdx.x;
    const int n4 = NNODES * COUT / 4;
    float4 z = make_float4(0.f, 0.f, 0.f, 0.f);
    if (i < n4) reinterpret_cast<float4*>(a)[i] = z;
    else if (i < 2 * n4) reinterpret_cast<float4*>(b)[i - n4] = z;
}

// X fp32 [N][128] -> fp16 [N][128]
__global__ void prepA_kernel(const float* __restrict__ X, __half* __restrict__ Ah) {
    int i = blockIdx.x * blockDim.x + threadIdx.x;   // over N*32 float4s
    if (i >= NNODES * 32) return;
    float4 x = reinterpret_cast<const float4*>(X)[i];
    reinterpret_cast<__half2*>(Ah)[i * 2] =
        __halves2half2(__float2half_rn(x.x), __float2half_rn(x.y));
    reinterpret_cast<__half2*>(Ah)[i * 2 + 1] =
        __halves2half2(__float2half_rn(x.z), __float2half_rn(x.w));
}

// all weights in one pass: W1 (9x128x128) -> WbA dirs 0-8; W2 -> Wb2; W3 -> WbA dir 9
__global__ void prepW_all_kernel(const float* __restrict__ W1, const float* __restrict__ W2,
                                 const float* __restrict__ W3,
                                 __half* __restrict__ WbA, __half* __restrict__ Wb2) {
    const int NW = NDIR * 128 * 128;  // 147456
    int idx = blockIdx.x * blockDim.x + threadIdx.x;
    if (idx < NW) {
        int d = idx >> 14, k = (idx >> 7) & 127, c = idx & 127;
        WbA[((size_t)d * 128 + c) * 128 + k] = __float2half_rn(W1[idx]);
    } else if (idx < 2 * NW) {
        int j = idx - NW;
        int d = j >> 14, k = (j >> 7) & 127, c = j & 127;
        Wb2[((size_t)d * 128 + c) * 128 + k] = __float2half_rn(W2[j]);
    } else if (idx < 2 * NW + 128 * 128) {
        int j = idx - 2 * NW;
        int k = j >> 7, c = j & 127;
        WbA[((size_t)NDIR * 128 + c) * 128 + k] = __float2half_rn(W3[j]);
    }
}

// ---------------- fused BN(eval) + ELU ----------------
__device__ __forceinline__ float elu1(float t) { return t > 0.f ? t : expm1f(t); }

// layer-1: acc -> fp16 features for layer 2; re-zero acc in place for reuse
__global__ void bnelu_prep_kernel(float* __restrict__ acc, const float* __restrict__ b,
                                  const float* __restrict__ g, const float* __restrict__ be,
                                  const float* __restrict__ rm, const float* __restrict__ rv,
                                  __half* __restrict__ Ah) {
    int i = blockIdx.x * blockDim.x + threadIdx.x;
    if (i >= NNODES * COUT / 4) return;
    float4 v = reinterpret_cast<const float4*>(acc)[i];
    int c0 = (i * 4) & (COUT - 1);
    float o[4] = {v.x, v.y, v.z, v.w};
    float rr[4];
#pragma unroll
    for (int j = 0; j < 4; j++) {
        int c = c0 + j;
        float s = __ldg(g + c) * rsqrtf(__ldg(rv + c) + 1e-5f);
        float t = (o[j] + __ldg(b + c) - __ldg(rm + c)) * s + __ldg(be + c);
        rr[j] = elu1(t);
    }
    reinterpret_cast<__half2*>(Ah)[i * 2] =
        __halves2half2(__float2half_rn(rr[0]), __float2half_rn(rr[1]));
    reinterpret_cast<__half2*>(Ah)[i * 2 + 1] =
        __halves2half2(__float2half_rn(rr[2]), __float2half_rn(rr[3]));
    reinterpret_cast<float4*>(acc)[i] = make_float4(0.f, 0.f, 0.f, 0.f);
}

// fused layer-2 BN/ELU + shortcut combine + BN3/ELU:
// out = ELU(BN3( ELU(BN2(acc + b2)) + acc3 + b3 ))
__global__ void final2_kernel(const float* __restrict__ acc, const float* __restrict__ acc3,
                              const float* __restrict__ b2, const float* __restrict__ g2,
                              const float* __restrict__ be2, const float* __restrict__ rm2,
                              const float* __restrict__ rv2,
                              const float* __restrict__ b3, const float* __restrict__ g3,
                              const float* __restrict__ be3, const float* __restrict__ rm3,
                              const float* __restrict__ rv3,
                              float* __restrict__ out) {
    int i = blockIdx.x * blockDim.x + threadIdx.x;
    if (i >= NNODES * COUT / 4) return;
    float4 a = reinterpret_cast<const float4*>(acc)[i];
    float4 c4 = reinterpret_cast<const float4*>(acc3)[i];
    int c0 = (i * 4) & (COUT - 1);
    float av[4] = {a.x, a.y, a.z, a.w};
    float sv[4] = {c4.x, c4.y, c4.z, c4.w};
    float4 r;
    float* rr = reinterpret_cast<float*>(&r);
#pragma unroll
    for (int j = 0; j < 4; j++) {
        int c = c0 + j;
        float s2 = __ldg(g2 + c) * rsqrtf(__ldg(rv2 + c) + 1e-5f);
        float h = elu1((av[j] + __ldg(b2 + c) - __ldg(rm2 + c)) * s2 + __ldg(be2 + c));
        float s3 = __ldg(g3 + c) * rsqrtf(__ldg(rv3 + c) + 1e-5f);
        float t = (h + sv[j] + __ldg(b3 + c) - __ldg(rm3 + c)) * s3 + __ldg(be3 + c);
        rr[j] = elu1(t);
    }
    reinterpret_cast<float4*>(out)[i] = r;
}

// ---------------- launch ----------------
extern "C" void kernel_launch(void* const* d_in, const int* in_sizes, int n_in,
                              void* d_out, int out_size) {
    const float* x   = (const float*)d_in[0];
    const int*   ei  = (const int*)d_in[1];
    const int*   sel = (const int*)d_in[2];
    const float* W1  = (const float*)d_in[3];
    const float* b1  = (const float*)d_in[4];
    const float* g1  = (const float*)d_in[5];
    const float* be1 = (const float*)d_in[6];
    const float* rm1 = (const float*)d_in[7];
    const float* rv1 = (const float*)d_in[8];
    const float* W2  = (const float*)d_in[9];
    const float* b2  = (const float*)d_in[10];
    const float* g2  = (const float*)d_in[11];
    const float* be2 = (const float*)d_in[12];
    const float* rm2 = (const float*)d_in[13];
    const float* rv2 = (const float*)d_in[14];
    const float* W3  = (const float*)d_in[15];
    const float* b3  = (const float*)d_in[16];
    const float* g3  = (const float*)d_in[17];
    const float* be3 = (const float*)d_in[18];
    const float* rm3 = (const float*)d_in[19];
    const float* rv3 = (const float*)d_in[20];
    float* out = (float*)d_out;

    const int E = in_sizes[2];
    const int* src = ei;
    const int* dst = ei + E;

    float *acc, *acc3;
    __half *Abx, *Abh, *WbA, *Wb2;
    int *cnt, *boffs, *cur;
    uint32_t *ebuf;
    cudaGetSymbolAddress((void**)&acc, g_acc);
    cudaGetSymbolAddress((void**)&acc3, g_acc3);
    cudaGetSymbolAddress((void**)&Abx, g_Abx);
    cudaGetSymbolAddress((void**)&Abh, g_Abh);
    cudaGetSymbolAddress((void**)&WbA, g_WbA);
    cudaGetSymbolAddress((void**)&Wb2, g_Wb2);
    cudaGetSymbolAddress((void**)&cnt, g_cnt);
    cudaGetSymbolAddress((void**)&boffs, g_boffs);
    cudaGetSymbolAddress((void**)&cur, g_cur);
    cudaGetSymbolAddress((void**)&ebuf, g_ebuf);

    cudaFuncSetAttribute(gemm_scatter_kernel<true>,
                         cudaFuncAttributeMaxDynamicSharedMemorySize, SMEM_BYTES);
    cudaFuncSetAttribute(gemm_scatter_kernel<false>,
                         cudaFuncAttributeMaxDynamicSharedMemorySize, SMEM_BYTES);

    const int nc4 = NNODES * COUT / 4;
    const int ew_blocks = (nc4 + 255) / 256;
    const int z2_blocks = (2 * nc4 + 255) / 256;
    const int prepA_blocks = (NNODES * 32 + 255) / 256;
    const int prepW_blocks = (2 * NDIR * 128 * 128 + 128 * 128 + 255) / 256;
    const int e_blocks = (E + 255) / 256;

    // ---- prep + bucketing ----
    cudaMemsetAsync(cnt, 0, NBUCK * sizeof(int));
    prepW_all_kernel<<<prepW_blocks, 256>>>(W1, W2, W3, WbA, Wb2);
    prepA_kernel<<<prepA_blocks, 256>>>(x, Abx);
    hist_kernel<<<e_blocks, 256>>>(src, sel, cnt, E);
    scan_kernel<<<1, 256>>>(cnt, boffs, cur);
    fill_kernel<<<e_blocks, 256>>>(src, dst, sel, cur, ebuf, E);
    zero_both_kernel<<<z2_blocks, 256>>>(acc, acc3);

    // ---- layer 1 (9-dir) + shortcut (dir 9 = W3, sel-0 edges -> acc3) ----
    gemm_scatter_kernel<true><<<dim3(NDIR + 1, NTILES), 256, SMEM_BYTES>>>(
        Abx, WbA, boffs, ebuf, acc, acc3);
    bnelu_prep_kernel<<<ew_blocks, 256>>>(acc, b1, g1, be1, rm1, rv1, Abh);

    // ---- layer 2 (9-dir) ----
    gemm_scatter_kernel<false><<<dim3(NDIR, NTILES), 256, SMEM_BYTES>>>(
        Abh, Wb2, boffs, ebuf, acc, acc3);

    // ---- combine: ELU(BN3(ELU(BN2(acc+b2)) + acc3 + b3)) ----
    final2_kernel<<<ew_blocks, 256>>>(acc, acc3, b2, g2, be2, rm2, rv2,
                                      b3, g3, be3, rm3, rv3, out);
}

// round 7
// speedup vs baseline: 4.0794x; 1.0402x over previous
#include <cuda_runtime.h>
#include <cuda_fp16.h>
#include <cstdint>
#include <cstddef>

#define NNODES 65536
#define CIN    128
#define COUT   128
#define NDIR   9
#define NTILES (NNODES / 64)         // 1024 tiles of 64 nodes
#define NBUCK  (NTILES * NDIR)       // 9216
#define EMAX   1048576

// ---------------- scratch (static device globals; no allocation) ----------------
__device__ __align__(256) float g_acc[(size_t)NNODES * COUT];
__device__ __align__(256) float g_acc3[(size_t)NNODES * COUT];
__device__ __align__(256) __half g_Abx[(size_t)NNODES * 128]; // fp16 features
__device__ __align__(256) __half g_Abh[(size_t)NNODES * 128];
__device__ __align__(256) __half g_WbA[(size_t)(NDIR + 1) * 128 * 128]; // W1 dirs 0-8, W3 as dir 9
__device__ __align__(256) __half g_Wb2[(size_t)NDIR * 128 * 128];
__device__ int g_cnt[NBUCK];
__device__ int g_boffs[NBUCK + 1];
__device__ int g_cur[NBUCK];
__device__ uint32_t g_ebuf[EMAX];    // packed: dst[0:16) | localsrc[16:22)

// ---------------- PTX helpers ----------------
__device__ __forceinline__ uint32_t smem_u32(const void* p) {
    uint32_t a;
    asm("{ .reg .u64 t; cvta.to.shared.u64 t, %1; cvt.u32.u64 %0, t; }" : "=r"(a) : "l"(p));
    return a;
}
__device__ __forceinline__ void cp_async16(uint32_t saddr, const void* gptr) {
    asm volatile("cp.async.cg.shared.global [%0], [%1], 16;" :: "r"(saddr), "l"(gptr) : "memory");
}
__device__ __forceinline__ void cp_commit() {
    asm volatile("cp.async.commit_group;" ::: "memory");
}
template <int N>
__device__ __forceinline__ void cp_wait() {
    asm volatile("cp.async.wait_group %0;" :: "n"(N) : "memory");
}
__device__ __forceinline__ void ldsm_x4(uint32_t* r, uint32_t addr) {
    asm volatile("ldmatrix.sync.aligned.m8n8.x4.shared.b16 {%0,%1,%2,%3}, [%4];"
                 : "=r"(r[0]), "=r"(r[1]), "=r"(r[2]), "=r"(r[3]) : "r"(addr));
}
__device__ __forceinline__ void mma16816(float* d, const uint32_t* a, const uint32_t* b) {
    asm volatile(
        "mma.sync.aligned.m16n8k16.row.col.f32.f16.f16.f32 "
        "{%0,%1,%2,%3}, {%4,%5,%6,%7}, {%8,%9}, {%0,%1,%2,%3};"
        : "+f"(d[0]), "+f"(d[1]), "+f"(d[2]), "+f"(d[3])
        : "r"(a[0]), "r"(a[1]), "r"(a[2]), "r"(a[3]), "r"(b[0]), "r"(b[1]));
}

// SMEM layout (dynamic, 1024-aligned base):
//   [0, 8K)   A chunk0 | [8K,16K) A chunk1 | [16K,32K) B chunk0 | [32K,48K) B chunk1
//   after mainloop, region reused as Y tile: float[64][132] (33.8KB)
static constexpr int YSTRIDE = 132;
static constexpr int SMEM_BYTES = 1024 + 49152;   // 50176 -> 4 CTAs/SM

// ---------------- fused GEMM + scatter ----------------
// grid = (ndirs, 1024). CTA computes Y tile [64 nodes x 128 cols] for weight block
// blockIdx.x (K=128 fp16), then scatters bucket edges into the accumulator.
// WITH_SC: blockIdx.x == NDIR means shortcut (W3): bucket dir 0, target acc3.
template <bool WITH_SC>
__global__ void __launch_bounds__(128, 4)
gemm_scatter_kernel(const __half* __restrict__ Ab,   // [N][128] fp16
                    const __half* __restrict__ Bb,   // [(ndirs)*128][128] fp16, k contiguous
                    const int* __restrict__ boffs,
                    const uint32_t* __restrict__ ebuf,
                    float* __restrict__ gacc,
                    float* __restrict__ gacc3)
{
    extern __shared__ char smem_raw[];
    char* sdata = (char*)(((uintptr_t)smem_raw + 1023) & ~(uintptr_t)1023);
    const uint32_t sb = smem_u32(sdata);

    const int tid = threadIdx.x;
    const int wid = tid >> 5, lane = tid & 31;
    const int warpM = wid & 1;        // 2 warps over M (32 rows each)
    const int warpN = wid >> 1;       // 2 warps over N (64 cols each)
    const int rowBase = blockIdx.y << 6;
    const int colBase = blockIdx.x << 7;   // weight row block
    const bool sc = WITH_SC && (blockIdx.x == NDIR);
    const int bdir = sc ? 0 : blockIdx.x;
    const int bucket = blockIdx.y * NDIR + bdir;
    float* target = sc ? gacc3 : gacc;

    float cfrag[2][8][4];
#pragma unroll
    for (int mt = 0; mt < 2; mt++)
#pragma unroll
        for (int nt = 0; nt < 8; nt++)
#pragma unroll
            for (int j = 0; j < 4; j++) cfrag[mt][nt][j] = 0.f;

    auto load_A = [&](int c) {
        uint32_t aBase = sb + (uint32_t)c * 8192;
#pragma unroll
        for (int i = 0; i < 4; i++) {
            int idx = tid + (i << 7);          // 0..511
            int row = idx >> 3, g = idx & 7;   // row 0..63, 16B group
            uint32_t so = (uint32_t)row * 128 + (uint32_t)((g ^ (row & 7)) << 4);
            cp_async16(aBase + so, Ab + (size_t)(rowBase + row) * 128 + c * 64 + g * 8);
        }
    };
    auto load_B = [&]() {
#pragma unroll
        for (int i = 0; i < 16; i++) {
            int idx = tid + (i << 7);          // 0..2047
            int ch = idx >> 10;                // chunk 0/1
            int row = (idx >> 3) & 127, g = idx & 7;
            uint32_t so = 16384u + (uint32_t)ch * 16384 + (uint32_t)row * 128
                        + (uint32_t)((g ^ (row & 7)) << 4);
            cp_async16(sb + so, Bb + (size_t)(colBase + row) * 128 + ch * 64 + g * 8);
        }
    };

    load_B();
    load_A(0);
    cp_commit();
    load_A(1);
    cp_commit();

#pragma unroll
    for (int c = 0; c < 2; c++) {
        if (c == 0) cp_wait<1>();
        else        cp_wait<0>();
        __syncthreads();

        uint32_t aBase = sb + (uint32_t)c * 8192;
        uint32_t bBase = sb + 16384u + (uint32_t)c * 16384;

#pragma unroll
        for (int ks = 0; ks < 4; ks++) {
            uint32_t aF[2][4];
#pragma unroll
            for (int mt = 0; mt < 2; mt++) {
                int row = warpM * 32 + mt * 16 + (lane & 15);
                int g = ks * 2 + (lane >> 4);
                ldsm_x4(aF[mt], aBase + (uint32_t)row * 128 + (uint32_t)((g ^ (row & 7)) << 4));
            }
            uint32_t bF[8][2];
#pragma unroll
            for (int p = 0; p < 4; p++) {
                int n = warpN * 64 + p * 16 + ((lane >> 4) << 3) + (lane & 7);
                int g = ks * 2 + ((lane >> 3) & 1);
                uint32_t r[4];
                ldsm_x4(r, bBase + (uint32_t)n * 128 + (uint32_t)((g ^ (n & 7)) << 4));
                bF[2 * p][0] = r[0]; bF[2 * p][1] = r[1];
                bF[2 * p + 1][0] = r[2]; bF[2 * p + 1][1] = r[3];
            }
#pragma unroll
            for (int mt = 0; mt < 2; mt++)
#pragma unroll
                for (int nt = 0; nt < 8; nt++)
                    mma16816(cfrag[mt][nt], aF[mt], bF[nt]);
        }
    }
    __syncthreads();   // all ldsm reads done before Y-tile overwrite

    // ---- write Y tile to SMEM (reuse pipeline region) ----
    float* yt = reinterpret_cast<float*>(sdata);
#pragma unroll
    for (int mt = 0; mt < 2; mt++) {
        int r0 = warpM * 32 + mt * 16 + (lane >> 2);
#pragma unroll
        for (int nt = 0; nt < 8; nt++) {
            int c0 = warpN * 64 + nt * 8 + ((lane & 3) << 1);
            yt[r0 * YSTRIDE + c0]       = cfrag[mt][nt][0];
            yt[r0 * YSTRIDE + c0 + 1]   = cfrag[mt][nt][1];
            yt[(r0 + 8) * YSTRIDE + c0]     = cfrag[mt][nt][2];
            yt[(r0 + 8) * YSTRIDE + c0 + 1] = cfrag[mt][nt][3];
        }
    }
    __syncthreads();

    // ---- scatter this bucket's edges (4 warps, stride 4) ----
    const int e0 = __ldg(boffs + bucket);
    const int e1 = __ldg(boffs + bucket + 1);
    for (int e = e0 + wid; e < e1; e += 4) {
        uint32_t pk = __ldg(ebuf + e);
        int ls = (pk >> 16) & 63;      // local src row (0..63)
        int dst = pk & 0xFFFF;
        float4 v = *reinterpret_cast<const float4*>(yt + (size_t)ls * YSTRIDE + lane * 4);
        float* op = target + (size_t)dst * COUT + lane * 4;
        asm volatile("red.global.add.v4.f32 [%0], {%1,%2,%3,%4};"
                     :: "l"(op), "f"(v.x), "f"(v.y), "f"(v.z), "f"(v.w)
                     : "memory");
    }
}

// ---------------- edge bucketing ----------------
__global__ void hist_kernel(const int* __restrict__ src, const int* __restrict__ sel,
                            int* __restrict__ cnt, int E) {
    int i = blockIdx.x * blockDim.x + threadIdx.x;
    if (i >= E) return;
    int b = (__ldg(src + i) >> 6) * NDIR + __ldg(sel + i);
    atomicAdd(cnt + b, 1);
}

__global__ void scan_kernel(const int* __restrict__ cnt, int* __restrict__ boffs,
                            int* __restrict__ cur) {
    __shared__ int part[256];
    __shared__ int partpf[257];
    const int PER = NBUCK / 256;   // 36
    int t = threadIdx.x;
    int base = t * PER;
    int loc[PER];
    int s = 0;
#pragma unroll
    for (int j = 0; j < PER; j++) { loc[j] = s; s += cnt[base + j]; }
    part[t] = s;
    __syncthreads();
    // warp 0 scans the 256 partials (8 per lane + shuffle scan)
    if (t < 32) {
        int tmp[8];
        int sum8 = 0;
        int b8 = t * 8;
#pragma unroll
        for (int j = 0; j < 8; j++) { tmp[j] = sum8; sum8 += part[b8 + j]; }
        int v = sum8;
#pragma unroll
        for (int off = 1; off < 32; off <<= 1) {
            int u = __shfl_up_sync(0xFFFFFFFFu, v, off);
            if (t >= off) v += u;
        }
        int excl = v - sum8;
#pragma unroll
        for (int j = 0; j < 8; j++) partpf[b8 + j] = excl + tmp[j];
        if (t == 31) partpf[256] = v;
    }
    __syncthreads();
    int off = partpf[t];
#pragma unroll
    for (int j = 0; j < PER; j++) {
        int v = off + loc[j];
        boffs[base + j] = v;
        cur[base + j] = v;
    }
    if (t == 255) boffs[NBUCK] = partpf[256];
}

__global__ void fill_kernel(const int* __restrict__ src, const int* __restrict__ dst,
                            const int* __restrict__ sel, int* __restrict__ cur,
                            uint32_t* __restrict__ ebuf, int E) {
    int i = blockIdx.x * blockDim.x + threadIdx.x;
    if (i >= E) return;
    int s = __ldg(src + i);
    int b = (s >> 6) * NDIR + __ldg(sel + i);
    int p = atomicAdd(cur + b, 1);
    ebuf[p] = (uint32_t)(__ldg(dst + i) & 0xFFFF) | ((uint32_t)(s & 63) << 16);
}

// ---------------- prep kernels ----------------
__global__ void zero_both_kernel(float* __restrict__ a, float* __restrict__ b) {
    int i = blockIdx.x * blockDim.x + threadIdx.x;
    const int n4 = NNODES * COUT / 4;
    float4 z = make_float4(0.f, 0.f, 0.f, 0.f);
    if (i < n4) reinterpret_cast<float4*>(a)[i] = z;
    else if (i < 2 * n4) reinterpret_cast<float4*>(b)[i - n4] = z;
}

// X fp32 [N][128] -> fp16 [N][128]
__global__ void prepA_kernel(const float* __restrict__ X, __half* __restrict__ Ah) {
    int i = blockIdx.x * blockDim.x + threadIdx.x;   // over N*32 float4s
    if (i >= NNODES * 32) return;
    float4 x = reinterpret_cast<const float4*>(X)[i];
    reinterpret_cast<__half2*>(Ah)[i * 2] =
        __halves2half2(__float2half_rn(x.x), __float2half_rn(x.y));
    reinterpret_cast<__half2*>(Ah)[i * 2 + 1] =
        __halves2half2(__float2half_rn(x.z), __float2half_rn(x.w));
}

// all weights in one pass: W1 (9x128x128) -> WbA dirs 0-8; W2 -> Wb2; W3 -> WbA dir 9
__global__ void prepW_all_kernel(const float* __restrict__ W1, const float* __restrict__ W2,
                                 const float* __restrict__ W3,
                                 __half* __restrict__ WbA, __half* __restrict__ Wb2) {
    const int NW = NDIR * 128 * 128;  // 147456
    int idx = blockIdx.x * blockDim.x + threadIdx.x;
    if (idx < NW) {
        int d = idx >> 14, k = (idx >> 7) & 127, c = idx & 127;
        WbA[((size_t)d * 128 + c) * 128 + k] = __float2half_rn(W1[idx]);
    } else if (idx < 2 * NW) {
        int j = idx - NW;
        int d = j >> 14, k = (j >> 7) & 127, c = j & 127;
        Wb2[((size_t)d * 128 + c) * 128 + k] = __float2half_rn(W2[j]);
    } else if (idx < 2 * NW + 128 * 128) {
        int j = idx - 2 * NW;
        int k = j >> 7, c = j & 127;
        WbA[((size_t)NDIR * 128 + c) * 128 + k] = __float2half_rn(W3[j]);
    }
}

// ---------------- fused BN(eval) + ELU ----------------
__device__ __forceinline__ float elu1(float t) { return t > 0.f ? t : expm1f(t); }

// layer-1: acc -> fp16 features for layer 2; re-zero acc in place for reuse
__global__ void bnelu_prep_kernel(float* __restrict__ acc, const float* __restrict__ b,
                                  const float* __restrict__ g, const float* __restrict__ be,
                                  const float* __restrict__ rm, const float* __restrict__ rv,
                                  __half* __restrict__ Ah) {
    int i = blockIdx.x * blockDim.x + threadIdx.x;
    if (i >= NNODES * COUT / 4) return;
    float4 v = reinterpret_cast<const float4*>(acc)[i];
    int c0 = (i * 4) & (COUT - 1);
    float o[4] = {v.x, v.y, v.z, v.w};
    float rr[4];
#pragma unroll
    for (int j = 0; j < 4; j++) {
        int c = c0 + j;
        float s = __ldg(g + c) * rsqrtf(__ldg(rv + c) + 1e-5f);
        float t = (o[j] + __ldg(b + c) - __ldg(rm + c)) * s + __ldg(be + c);
        rr[j] = elu1(t);
    }
    reinterpret_cast<__half2*>(Ah)[i * 2] =
        __halves2half2(__float2half_rn(rr[0]), __float2half_rn(rr[1]));
    reinterpret_cast<__half2*>(Ah)[i * 2 + 1] =
        __halves2half2(__float2half_rn(rr[2]), __float2half_rn(rr[3]));
    reinterpret_cast<float4*>(acc)[i] = make_float4(0.f, 0.f, 0.f, 0.f);
}

// fused layer-2 BN/ELU + shortcut combine + BN3/ELU:
// out = ELU(BN3( ELU(BN2(acc + b2)) + acc3 + b3 ))
__global__ void final2_kernel(const float* __restrict__ acc, const float* __restrict__ acc3,
                              const float* __restrict__ b2, const float* __restrict__ g2,
                              const float* __restrict__ be2, const float* __restrict__ rm2,
                              const float* __restrict__ rv2,
                              const float* __restrict__ b3, const float* __restrict__ g3,
                              const float* __restrict__ be3, const float* __restrict__ rm3,
                              const float* __restrict__ rv3,
                              float* __restrict__ out) {
    int i = blockIdx.x * blockDim.x + threadIdx.x;
    if (i >= NNODES * COUT / 4) return;
    float4 a = reinterpret_cast<const float4*>(acc)[i];
    float4 c4 = reinterpret_cast<const float4*>(acc3)[i];
    int c0 = (i * 4) & (COUT - 1);
    float av[4] = {a.x, a.y, a.z, a.w};
    float sv[4] = {c4.x, c4.y, c4.z, c4.w};
    float4 r;
    float* rr = reinterpret_cast<float*>(&r);
#pragma unroll
    for (int j = 0; j < 4; j++) {
        int c = c0 + j;
        float s2 = __ldg(g2 + c) * rsqrtf(__ldg(rv2 + c) + 1e-5f);
        float h = elu1((av[j] + __ldg(b2 + c) - __ldg(rm2 + c)) * s2 + __ldg(be2 + c));
        float s3 = __ldg(g3 + c) * rsqrtf(__ldg(rv3 + c) + 1e-5f);
        float t = (h + sv[j] + __ldg(b3 + c) - __ldg(rm3 + c)) * s3 + __ldg(be3 + c);
        rr[j] = elu1(t);
    }
    reinterpret_cast<float4*>(out)[i] = r;
}

// ---------------- launch ----------------
extern "C" void kernel_launch(void* const* d_in, const int* in_sizes, int n_in,
                              void* d_out, int out_size) {
    const float* x   = (const float*)d_in[0];
    const int*   ei  = (const int*)d_in[1];
    const int*   sel = (const int*)d_in[2];
    const float* W1  = (const float*)d_in[3];
    const float* b1  = (const float*)d_in[4];
    const float* g1  = (const float*)d_in[5];
    const float* be1 = (const float*)d_in[6];
    const float* rm1 = (const float*)d_in[7];
    const float* rv1 = (const float*)d_in[8];
    const float* W2  = (const float*)d_in[9];
    const float* b2  = (const float*)d_in[10];
    const float* g2  = (const float*)d_in[11];
    const float* be2 = (const float*)d_in[12];
    const float* rm2 = (const float*)d_in[13];
    const float* rv2 = (const float*)d_in[14];
    const float* W3  = (const float*)d_in[15];
    const float* b3  = (const float*)d_in[16];
    const float* g3  = (const float*)d_in[17];
    const float* be3 = (const float*)d_in[18];
    const float* rm3 = (const float*)d_in[19];
    const float* rv3 = (const float*)d_in[20];
    float* out = (float*)d_out;

    const int E = in_sizes[2];
    const int* src = ei;
    const int* dst = ei + E;

    float *acc, *acc3;
    __half *Abx, *Abh, *WbA, *Wb2;
    int *cnt, *boffs, *cur;
    uint32_t *ebuf;
    cudaGetSymbolAddress((void**)&acc, g_acc);
    cudaGetSymbolAddress((void**)&acc3, g_acc3);
    cudaGetSymbolAddress((void**)&Abx, g_Abx);
    cudaGetSymbolAddress((void**)&Abh, g_Abh);
    cudaGetSymbolAddress((void**)&WbA, g_WbA);
    cudaGetSymbolAddress((void**)&Wb2, g_Wb2);
    cudaGetSymbolAddress((void**)&cnt, g_cnt);
    cudaGetSymbolAddress((void**)&boffs, g_boffs);
    cudaGetSymbolAddress((void**)&cur, g_cur);
    cudaGetSymbolAddress((void**)&ebuf, g_ebuf);

    cudaFuncSetAttribute(gemm_scatter_kernel<true>,
                         cudaFuncAttributeMaxDynamicSharedMemorySize, SMEM_BYTES);
    cudaFuncSetAttribute(gemm_scatter_kernel<false>,
                         cudaFuncAttributeMaxDynamicSharedMemorySize, SMEM_BYTES);

    const int nc4 = NNODES * COUT / 4;
    const int ew_blocks = (nc4 + 255) / 256;
    const int z2_blocks = (2 * nc4 + 255) / 256;
    const int prepA_blocks = (NNODES * 32 + 255) / 256;
    const int prepW_blocks = (2 * NDIR * 128 * 128 + 128 * 128 + 255) / 256;
    const int e_blocks = (E + 255) / 256;

    // ---- prep + bucketing ----
    cudaMemsetAsync(cnt, 0, NBUCK * sizeof(int));
    prepW_all_kernel<<<prepW_blocks, 256>>>(W1, W2, W3, WbA, Wb2);
    prepA_kernel<<<prepA_blocks, 256>>>(x, Abx);
    hist_kernel<<<e_blocks, 256>>>(src, sel, cnt, E);
    scan_kernel<<<1, 256>>>(cnt, boffs, cur);
    fill_kernel<<<e_blocks, 256>>>(src, dst, sel, cur, ebuf, E);
    zero_both_kernel<<<z2_blocks, 256>>>(acc, acc3);

    // ---- layer 1 (9-dir) + shortcut (dir 9 = W3, sel-0 edges -> acc3) ----
    gemm_scatter_kernel<true><<<dim3(NDIR + 1, NTILES), 128, SMEM_BYTES>>>(
        Abx, WbA, boffs, ebuf, acc, acc3);
    bnelu_prep_kernel<<<ew_blocks, 256>>>(acc, b1, g1, be1, rm1, rv1, Abh);

    // ---- layer 2 (9-dir) ----
    gemm_scatter_kernel<false><<<dim3(NDIR, NTILES), 128, SMEM_BYTES>>>(
        Abh, Wb2, boffs, ebuf, acc, acc3);

    // ---- combine: ELU(BN3(ELU(BN2(acc+b2)) + acc3 + b3)) ----
    final2_kernel<<<ew_blocks, 256>>>(acc, acc3, b2, g2, be2, rm2, rv2,
                                      b3, g3, be3, rm3, rv3, out);
}